// round 7
// baseline (speedup 1.0000x reference)
#include <cuda_runtime.h>
#include <math.h>

// Problem constants
#define B      16
#define C      3
#define H      256
#define W      256
#define HW     65536      // 256*256
#define D      196608     // C*H*W
#define NEXP   4
#define TOPK   2
#define HID    64
#define FC     6

// ---------------- device scratch (no allocations allowed) ----------------
__device__ float g_refsum[B * C];   // per (b,c) sum over spatial of ref
__device__ float g_scale[B * C];    // 1 + prompt[b,c]
__device__ float g_logits[B * 8];   // [b][0..3]=clean, [4..7]=raw noise logit
__device__ float g_gate[B * 2];     // top-2 gate values per batch
__device__ int   g_eidx[B * 2];     // top-2 expert indices per batch
__device__ int   g_counter;         // last-block-finalizes counter (self-resetting)

// ---------------- K1: sum ref over spatial per (b,c) ----------------
__global__ void k_refsum(const float* __restrict__ ref) {
    const float* p = ref + (size_t)blockIdx.x * HW;
    float s = 0.f;
    for (int i = threadIdx.x; i < HW; i += 256) s += p[i];
    __shared__ float sm[256];
    sm[threadIdx.x] = s;
    __syncthreads();
    for (int st = 128; st > 0; st >>= 1) {
        if (threadIdx.x < st) sm[threadIdx.x] += sm[threadIdx.x + st];
        __syncthreads();
    }
    if (threadIdx.x == 0) g_refsum[blockIdx.x] = sm[0];
}

// ---------------- K2: DC-bin prompt math (whole FFT chain collapsed) -----
__global__ void k_prompt(const float* __restrict__ mod_w1,
                         const float* __restrict__ mod_b1,
                         const float* __restrict__ mod_w2,
                         const float* __restrict__ mod_b2,
                         const float* __restrict__ enh_w,
                         const float* __restrict__ enh_b,
                         const float* __restrict__ fre_prompt) {
    int b = threadIdx.x;
    if (b >= B) return;
    float s[3];
#pragma unroll
    for (int c = 0; c < 3; c++) s[c] = g_refsum[b * 3 + c] * (1.f / 256.f);
    float p[12];
#pragma unroll
    for (int i = 0; i < 12; i++) {
        int ci = (i < 6) ? i : i - 6;
        p[i] = (ci < 3) ? s[ci] : 0.f;
    }
    float m1[6];
#pragma unroll
    for (int o = 0; o < 6; o++) {
        float a = mod_b1[o];
#pragma unroll
        for (int i = 0; i < 12; i++) a += mod_w1[o * 12 + i] * p[i];
        m1[o] = fmaxf(a, 0.f);
    }
    float m2[6];
#pragma unroll
    for (int o = 0; o < 6; o++) {
        float a = mod_b2[o];
#pragma unroll
        for (int i = 0; i < 6; i++) a += mod_w2[o * 6 + i] * m1[i];
        m2[o] = a;
    }
    float ein[6];
#pragma unroll
    for (int c = 0; c < 6; c++) ein[c] = m2[c] * fre_prompt[c * (H * (W / 2 + 1))];
    float enh[6];
#pragma unroll
    for (int o = 0; o < 6; o++) {
        float a = enh_b[o];
#pragma unroll
        for (int i = 0; i < 6; i++) a += enh_w[o * 6 + i] * ein[i];
        enh[o] = fmaxf(a, 0.f);
    }
    float v0 = enh[0] * (1.f / 256.f);
    float v1 = enh[1] * (1.f / 256.f);
    float v2 = enh[2] * (1.f / 256.f);
    float mx = fmaxf(v0, fmaxf(v1, v2));
    float e0 = expf(v0 - mx), e1 = expf(v1 - mx), e2 = expf(v2 - mx);
    float inv = 1.f / (e0 + e1 + e2);
    g_scale[b * 3 + 0] = 1.f + e0 * inv;
    g_scale[b * 3 + 1] = 1.f + e1 * inv;
    g_scale[b * 3 + 2] = 1.f + e2 * inv;
}

// ---------------- K3: gating matvecs + fused finalize ---------------------
__device__ __forceinline__ float cv2_4(float a, float b, float c, float d) {
    float m = (a + b + c + d) * 0.25f;
    float va = a - m, vb = b - m, vc = c - m, vd = d - m;
    float var = (va * va + vb * vb + vc * vc + vd * vd) * (1.f / 3.f);
    return var / (m * m + 1e-10f);
}

__global__ void k_gate_fin(const float* __restrict__ x,
                           const float* __restrict__ w_gate,
                           const float* __restrict__ w_noise,
                           const float* __restrict__ noise,
                           float* __restrict__ out, int out_size) {
    const int b = blockIdx.x;
    const int tid = threadIdx.x;
    const float sc0 = g_scale[b * 3 + 0];
    const float sc1 = g_scale[b * 3 + 1];
    const float sc2 = g_scale[b * 3 + 2];
    const float* xb = x + (size_t)b * D;
    float a[8] = {0, 0, 0, 0, 0, 0, 0, 0};
    const float4* wg4 = (const float4*)w_gate;
    const float4* wn4 = (const float4*)w_noise;
    for (int i = tid; i < D; i += 512) {
        float sc = (i < HW) ? sc0 : ((i < 2 * HW) ? sc1 : sc2);
        float xv = xb[i] * sc;
        float4 wg = wg4[i];
        float4 wn = wn4[i];
        a[0] += xv * wg.x; a[1] += xv * wg.y; a[2] += xv * wg.z; a[3] += xv * wg.w;
        a[4] += xv * wn.x; a[5] += xv * wn.y; a[6] += xv * wn.z; a[7] += xv * wn.w;
    }
    __shared__ float sm[512 * 8];
#pragma unroll
    for (int k = 0; k < 8; k++) sm[tid * 8 + k] = a[k];
    __syncthreads();
    for (int st = 256; st > 0; st >>= 1) {
        if (tid < st) {
#pragma unroll
            for (int k = 0; k < 8; k++) sm[tid * 8 + k] += sm[(tid + st) * 8 + k];
        }
        __syncthreads();
    }
    __shared__ int s_last;
    if (tid == 0) {
#pragma unroll
        for (int k = 0; k < 8; k++) g_logits[b * 8 + k] = sm[k];
        __threadfence();
        int prev = atomicAdd(&g_counter, 1);
        s_last = (prev == B - 1) ? 1 : 0;
    }
    __syncthreads();
    if (!s_last || tid >= 32) return;

    // ---- finalize (warp 0 of last-arriving block) ----
    __threadfence();
    const int lane = tid;
    float prob[4] = {0, 0, 0, 0};
    float gates[4] = {0, 0, 0, 0};
    if (lane < B) {
        const int bb = lane;
        float clean[4], stdv[4], noisy[4];
#pragma unroll
        for (int e = 0; e < 4; e++) {
            clean[e] = g_logits[bb * 8 + e];
            float z = g_logits[bb * 8 + 4 + e];
            float sp = (z > 0.f) ? (z + log1pf(expf(-z))) : log1pf(expf(z));
            stdv[e] = sp + 0.01f;
            noisy[e] = clean[e] + noise[bb * 4 + e] * stdv[e];
        }
        float v[4] = {noisy[0], noisy[1], noisy[2], noisy[3]};
        int idx[4] = {0, 1, 2, 3};
#pragma unroll
        for (int s = 0; s < 3; s++) {
            int m = s;
#pragma unroll
            for (int j = s + 1; j < 4; j++)
                if (v[j] > v[m]) m = j;
            float tv = v[s]; v[s] = v[m]; v[m] = tv;
            int ti = idx[s]; idx[s] = idx[m]; idx[m] = ti;
        }
        float t1 = v[1], t2 = v[2];
        float mx = fmaxf(v[0], v[1]);
        float e0 = expf(v[0] - mx), e1 = expf(v[1] - mx);
        float inv = 1.f / (e0 + e1);
        float gA = e0 * inv, gB = e1 * inv;
        gates[idx[0]] = gA;
        gates[idx[1]] = gB;
        g_eidx[bb * 2 + 0] = idx[0];
        g_eidx[bb * 2 + 1] = idx[1];
        g_gate[bb * 2 + 0] = gA;
        g_gate[bb * 2 + 1] = gB;
#pragma unroll
        for (int e = 0; e < 4; e++) {
            float thr = (noisy[e] > t2) ? t2 : t1;
            float z = (clean[e] - thr) / stdv[e];
            prob[e] = 0.5f * erfcf(-z * 0.70710678118654752f);
        }
    }
#pragma unroll
    for (int off = 16; off > 0; off >>= 1) {
#pragma unroll
        for (int e = 0; e < 4; e++) {
            prob[e]  += __shfl_down_sync(0xffffffffu, prob[e], off);
            gates[e] += __shfl_down_sync(0xffffffffu, gates[e], off);
        }
    }
    if (lane == 0) {
        float loss = (cv2_4(gates[0], gates[1], gates[2], gates[3]) +
                      cv2_4(prob[0], prob[1], prob[2], prob[3])) * 0.01f;
        if (out_size > B * HW) out[B * HW] = loss;
        g_counter = 0;      // self-reset for next launch / graph replay
        __threadfence();
    }
}

// ---------------- K5: fused sparse expert convs ---------------------------
// 288-thread blocks: conv1 16oc x 18rows = 288 tasks 1:1. conv2 task
// (cy, cicl) fixed per thread; partial row accumulates in registers across
// all 8 chunk-slots (gate-pre-scaled w2). Weights double-buffered: next
// chunk's w1/w2/b1 prefetched into registers during current chunk compute.
// 'part' overlays hs (dead after last conv2) -> 44KB smem/block.
#define TDIM 16
#define NTHR 288
#define XW   21    // padded x row stride
#define HWID 19    // padded h row stride
#define PICL 274   // part icl-stride (fits in hs: 16*274=4384 <= 5472)

__global__ void __launch_bounds__(NTHR, 3)
k_expert(const float* __restrict__ x,
         const float* __restrict__ ew1, const float* __restrict__ eb1,
         const float* __restrict__ ew2, const float* __restrict__ eb2,
         float* __restrict__ out) {
    const int b = blockIdx.z, tY = blockIdx.y, tX = blockIdx.x;
    const int tid = threadIdx.x;

    __shared__ float xs[3 * 20 * XW];     // 5040 f
    __shared__ float hs[16 * 18 * HWID];  // 5472 f (reused as 'part' at end)
    __shared__ float w1s[16 * 27];
    __shared__ float w2s[16 * 9];
    __shared__ float b1s[16];

    // load x tile (+halo 2), shared by both experts
    const int gy0 = tY * TDIM - 2, gx0 = tX * TDIM - 2;
    for (int i = tid; i < 3 * 20 * 20; i += NTHR) {
        int c = i / 400, r = (i / 20) % 20, col = i % 20;
        int gy = gy0 + r, gx = gx0 + col;
        float v = 0.f;
        if ((unsigned)gy < 256u && (unsigned)gx < 256u)
            v = x[((size_t)(b * 3 + c) << 16) + (gy << 8) + gx];
        xs[(c * 20 + r) * XW + col] = v;
    }

    const bool interior = (tY > 0) && (tY < H / TDIM - 1) &&
                          (tX > 0) && (tX < W / TDIM - 1);

    const int c1_ocl = tid / 18, c1_yy = tid % 18;   // conv1 task
    const int cy = tid >> 4, cicl = tid & 15;        // conv2 task (tid<256)

    const int   eA = g_eidx[b * 2 + 0], eB = g_eidx[b * 2 + 1];
    const float gA = g_gate[b * 2 + 0], gB = g_gate[b * 2 + 1];

    // prefetch chunk 0 weights (expert A, ch 0)
    float f0, f1 = 0.f, f2 = 0.f, f3 = 0.f;
    {
        const float* W1 = ew1 + eA * (HID * 27);
        f0 = W1[tid];
        if (tid < 144) f1 = W1[tid + NTHR];
        if (tid < 144) f2 = ew2[eB * 0 + eA * (HID * 9) + tid]; // ch0
        if (tid < 16)  f3 = eb1[eA * HID + tid];
    }

    float acc2[16];
#pragma unroll
    for (int j = 0; j < 16; j++) acc2[j] = 0.f;

    for (int it = 0; it < 8; it++) {
        const int slot = it >> 2;
        const float g = slot ? gB : gA;

        __syncthreads(); // prior conv2 reads of hs/w2s done (covers xs fill)
        w1s[tid] = f0;
        if (tid < 144) w1s[tid + NTHR] = f1;
        if (tid < 144) w2s[tid] = g * f2;
        if (tid < 16)  b1s[tid] = f3;

        // prefetch next chunk's weights (hidden under conv1+conv2)
        if (it < 7) {
            const int nit = it + 1;
            const int ne = (nit >> 2) ? eB : eA;
            const int nch = nit & 3;
            const float* W1 = ew1 + ne * (HID * 27) + nch * 432;
            f0 = W1[tid];
            if (tid < 144) f1 = W1[tid + NTHR];
            if (tid < 144) f2 = ew2[ne * (HID * 9) + nch * 144 + tid];
            if (tid < 16)  f3 = eb1[ne * HID + nch * 16 + tid];
        }
        __syncthreads(); // weights visible

        // conv1 + ReLU: one task per thread, sliding window over x rows
        {
            float acc[18];
            const float bias = b1s[c1_ocl];
#pragma unroll
            for (int j = 0; j < 18; j++) acc[j] = bias;
#pragma unroll
            for (int ic = 0; ic < 3; ic++) {
#pragma unroll
                for (int ky = 0; ky < 3; ky++) {
                    const float* row = &xs[(ic * 20 + c1_yy + ky) * XW];
                    const float* wp = &w1s[c1_ocl * 27 + ic * 9 + ky * 3];
                    const float wa = wp[0], wb = wp[1], wc = wp[2];
                    float r0 = row[0], r1 = row[1];
#pragma unroll
                    for (int j = 0; j < 18; j++) {
                        float r2 = row[j + 2];
                        acc[j] += r0 * wa + r1 * wb + r2 * wc;
                        r0 = r1; r1 = r2;
                    }
                }
            }
            float* hrow = &hs[(c1_ocl * 18 + c1_yy) * HWID];
            if (interior) {
#pragma unroll
                for (int j = 0; j < 18; j++) hrow[j] = fmaxf(acc[j], 0.f);
            } else {
                // conv2 SAME padding: h == 0 outside the image
                const bool rowok = (unsigned)(tY * TDIM + c1_yy - 1) < (unsigned)H;
#pragma unroll
                for (int j = 0; j < 18; j++) {
                    const bool ok = rowok &&
                        (unsigned)(tX * TDIM + j - 1) < (unsigned)W;
                    hrow[j] = ok ? fmaxf(acc[j], 0.f) : 0.f;
                }
            }
        }
        __syncthreads();

        // conv2 partial row into registers
        if (tid < 256) {
            const float* wp = &w2s[cicl * 9];
#pragma unroll
            for (int ky = 0; ky < 3; ky++) {
                const float* row = &hs[(cicl * 18 + cy + ky) * HWID];
                const float wa = wp[ky * 3], wb = wp[ky * 3 + 1], wc = wp[ky * 3 + 2];
                float r0 = row[0], r1 = row[1];
#pragma unroll
                for (int j = 0; j < 16; j++) {
                    float r2 = row[j + 2];
                    acc2[j] += r0 * wa + r1 * wb + r2 * wc;
                    r0 = r1; r1 = r2;
                }
            }
        }
    }

    __syncthreads(); // all hs reads done -> safe to overlay part onto hs
    float* part = hs;
    if (tid < 256) {
        float* pp = &part[cicl * PICL + cy * 17];
#pragma unroll
        for (int j = 0; j < 16; j++) pp[j] = acc2[j];
    }
    __syncthreads();

    if (tid < 256) {
        const int oy = tid >> 4, ox = tid & 15;
        float yacc = 0.f;
#pragma unroll
        for (int icl = 0; icl < 16; icl++)
            yacc += part[icl * PICL + oy * 17 + ox];
        yacc += gA * eb2[eA] + gB * eb2[eB];
        out[((size_t)b << 16) + ((tY * TDIM + oy) << 8) + (tX * TDIM + ox)] = yacc;
    }
}

// ---------------- no-op pad launch (keeps 5 launches/iteration) ----------
__global__ void k_noop() {}

// ---------------- launch ---------------------------------------------------
extern "C" void kernel_launch(void* const* d_in, const int* in_sizes, int n_in,
                              void* d_out, int out_size) {
    const float* x          = (const float*)d_in[0];
    const float* ref        = (const float*)d_in[1];
    const float* noise      = (const float*)d_in[2];
    const float* mod_w1     = (const float*)d_in[3];
    const float* mod_b1     = (const float*)d_in[4];
    const float* mod_w2     = (const float*)d_in[5];
    const float* mod_b2     = (const float*)d_in[6];
    const float* enh_w      = (const float*)d_in[7];
    const float* enh_b      = (const float*)d_in[8];
    const float* fre_prompt = (const float*)d_in[9];
    const float* w_gate     = (const float*)d_in[10];
    const float* w_noise    = (const float*)d_in[11];
    const float* ew1        = (const float*)d_in[12];
    const float* eb1        = (const float*)d_in[13];
    const float* ew2        = (const float*)d_in[14];
    const float* eb2        = (const float*)d_in[15];
    float* out = (float*)d_out;

    // position 3 = k_expert (the slot ncu's -s/-c capture has been hitting)
    k_refsum<<<B * C, 256>>>(ref);                                       // 0
    k_prompt<<<1, 32>>>(mod_w1, mod_b1, mod_w2, mod_b2,
                        enh_w, enh_b, fre_prompt);                       // 1
    k_gate_fin<<<B, 512>>>(x, w_gate, w_noise, noise, out, out_size);    // 2
    k_expert<<<dim3(W / TDIM, H / TDIM, B), NTHR>>>(x, ew1, eb1,
                                                    ew2, eb2, out);      // 3
    k_noop<<<1, 32>>>();                                                 // 4
}

// round 9
// speedup vs baseline: 1.0593x; 1.0593x over previous
#include <cuda_runtime.h>
#include <math.h>

// Problem constants
#define B      16
#define C      3
#define H      256
#define W      256
#define HW     65536      // 256*256
#define D      196608     // C*H*W
#define NEXP   4
#define TOPK   2
#define HID    64
#define FC     6

// ---------------- device scratch (no allocations allowed) ----------------
__device__ float g_refsum[B * C];   // per (b,c) sum over spatial of ref
__device__ float g_logits[B * 8];   // [b][0..3]=clean, [4..7]=raw noise logit
__device__ float g_gate[B * 2];     // top-2 gate values per batch
__device__ int   g_eidx[B * 2];     // top-2 expert indices per batch

// ---------------- K1: sum ref over spatial per (b,c), float4 loads -------
__global__ void k_refsum(const float* __restrict__ ref) {
    const float4* p = (const float4*)(ref + (size_t)blockIdx.x * HW);
    float s = 0.f;
    for (int i = threadIdx.x; i < HW / 4; i += 256) {
        float4 v = p[i];
        s += (v.x + v.y) + (v.z + v.w);
    }
    __shared__ float sm[256];
    sm[threadIdx.x] = s;
    __syncthreads();
    for (int st = 128; st > 0; st >>= 1) {
        if (threadIdx.x < st) sm[threadIdx.x] += sm[threadIdx.x + st];
        __syncthreads();
    }
    if (threadIdx.x == 0) g_refsum[blockIdx.x] = sm[0];
}

// ---------------- prompt math for one batch (FFT chain collapsed to DC) --
// spatial.mean of irfft2(Z, ortho) == Re(Z[0,0])/256; channel MLPs are
// pointwise in frequency -> only the DC bin matters.
__device__ void prompt_scales(int b,
                              const float* __restrict__ mod_w1,
                              const float* __restrict__ mod_b1,
                              const float* __restrict__ mod_w2,
                              const float* __restrict__ mod_b2,
                              const float* __restrict__ enh_w,
                              const float* __restrict__ enh_b,
                              const float* __restrict__ fre_prompt,
                              float* sc /*[3]*/) {
    float s[3];
#pragma unroll
    for (int c = 0; c < 3; c++) s[c] = g_refsum[b * 3 + c] * (1.f / 256.f);
    float p[12];
#pragma unroll
    for (int i = 0; i < 12; i++) {
        int ci = (i < 6) ? i : i - 6;
        p[i] = (ci < 3) ? s[ci] : 0.f;
    }
    float m1[6];
#pragma unroll
    for (int o = 0; o < 6; o++) {
        float a = mod_b1[o];
#pragma unroll
        for (int i = 0; i < 12; i++) a += mod_w1[o * 12 + i] * p[i];
        m1[o] = fmaxf(a, 0.f);
    }
    float m2[6];
#pragma unroll
    for (int o = 0; o < 6; o++) {
        float a = mod_b2[o];
#pragma unroll
        for (int i = 0; i < 6; i++) a += mod_w2[o * 6 + i] * m1[i];
        m2[o] = a;
    }
    float ein[6];
#pragma unroll
    for (int c = 0; c < 6; c++) ein[c] = m2[c] * fre_prompt[c * (H * (W / 2 + 1))];
    float enh[6];
#pragma unroll
    for (int o = 0; o < 6; o++) {
        float a = enh_b[o];
#pragma unroll
        for (int i = 0; i < 6; i++) a += enh_w[o * 6 + i] * ein[i];
        enh[o] = fmaxf(a, 0.f);
    }
    float v0 = enh[0] * (1.f / 256.f);
    float v1 = enh[1] * (1.f / 256.f);
    float v2 = enh[2] * (1.f / 256.f);
    float mx = fmaxf(v0, fmaxf(v1, v2));
    float e0 = expf(v0 - mx), e1 = expf(v1 - mx), e2 = expf(v2 - mx);
    float inv = 1.f / (e0 + e1 + e2);
    sc[0] = 1.f + e0 * inv;
    sc[1] = 1.f + e1 * inv;
    sc[2] = 1.f + e2 * inv;
}

// ---------------- K2: gating matvecs (prompt fused into head) ------------
__global__ void k_gate_dots(const float* __restrict__ x,
                            const float* __restrict__ w_gate,
                            const float* __restrict__ w_noise,
                            const float* __restrict__ mod_w1,
                            const float* __restrict__ mod_b1,
                            const float* __restrict__ mod_w2,
                            const float* __restrict__ mod_b2,
                            const float* __restrict__ enh_w,
                            const float* __restrict__ enh_b,
                            const float* __restrict__ fre_prompt) {
    const int b = blockIdx.x;
    const int tid = threadIdx.x;
    __shared__ float s_sc[3];
    if (tid == 0) {
        float sc[3];
        prompt_scales(b, mod_w1, mod_b1, mod_w2, mod_b2, enh_w, enh_b,
                      fre_prompt, sc);
        s_sc[0] = sc[0]; s_sc[1] = sc[1]; s_sc[2] = sc[2];
    }
    __syncthreads();
    const float sc0 = s_sc[0], sc1 = s_sc[1], sc2 = s_sc[2];
    const float* xb = x + (size_t)b * D;
    float a[8] = {0, 0, 0, 0, 0, 0, 0, 0};
    const float4* wg4 = (const float4*)w_gate;
    const float4* wn4 = (const float4*)w_noise;
    for (int i = tid; i < D; i += 512) {
        float sc = (i < HW) ? sc0 : ((i < 2 * HW) ? sc1 : sc2);
        float xv = xb[i] * sc;
        float4 wg = wg4[i];
        float4 wn = wn4[i];
        a[0] += xv * wg.x; a[1] += xv * wg.y; a[2] += xv * wg.z; a[3] += xv * wg.w;
        a[4] += xv * wn.x; a[5] += xv * wn.y; a[6] += xv * wn.z; a[7] += xv * wn.w;
    }
    __shared__ float sm[512 * 8];
#pragma unroll
    for (int k = 0; k < 8; k++) sm[tid * 8 + k] = a[k];
    __syncthreads();
    for (int st = 256; st > 0; st >>= 1) {
        if (tid < st) {
#pragma unroll
            for (int k = 0; k < 8; k++) sm[tid * 8 + k] += sm[(tid + st) * 8 + k];
        }
        __syncthreads();
    }
    if (tid == 0) {
#pragma unroll
        for (int k = 0; k < 8; k++) g_logits[b * 8 + k] = sm[k];
    }
}

// ---------------- K3: noisy top-k gating + load-balance loss -------------
__device__ __forceinline__ float cv2_4(float a, float b, float c, float d) {
    float m = (a + b + c + d) * 0.25f;
    float va = a - m, vb = b - m, vc = c - m, vd = d - m;
    float var = (va * va + vb * vb + vc * vc + vd * vd) * (1.f / 3.f);
    return var / (m * m + 1e-10f);
}

__global__ void k_finalize(const float* __restrict__ noise,
                           float* __restrict__ out, int out_size) {
    const int lane = threadIdx.x;
    float prob[4] = {0, 0, 0, 0};
    float gates[4] = {0, 0, 0, 0};
    if (lane < B) {
        const int b = lane;
        float clean[4], stdv[4], noisy[4];
#pragma unroll
        for (int e = 0; e < 4; e++) {
            clean[e] = g_logits[b * 8 + e];
            float z = g_logits[b * 8 + 4 + e];
            float sp = (z > 0.f) ? (z + log1pf(expf(-z))) : log1pf(expf(z));
            stdv[e] = sp + 0.01f;
            noisy[e] = clean[e] + noise[b * 4 + e] * stdv[e];
        }
        float v[4] = {noisy[0], noisy[1], noisy[2], noisy[3]};
        int idx[4] = {0, 1, 2, 3};
#pragma unroll
        for (int s = 0; s < 3; s++) {
            int m = s;
#pragma unroll
            for (int j = s + 1; j < 4; j++)
                if (v[j] > v[m]) m = j;
            float tv = v[s]; v[s] = v[m]; v[m] = tv;
            int ti = idx[s]; idx[s] = idx[m]; idx[m] = ti;
        }
        float t1 = v[1], t2 = v[2];
        float mx = fmaxf(v[0], v[1]);
        float e0 = expf(v[0] - mx), e1 = expf(v[1] - mx);
        float inv = 1.f / (e0 + e1);
        float gA = e0 * inv, gB = e1 * inv;
        gates[idx[0]] = gA;
        gates[idx[1]] = gB;
        g_eidx[b * 2 + 0] = idx[0];
        g_eidx[b * 2 + 1] = idx[1];
        g_gate[b * 2 + 0] = gA;
        g_gate[b * 2 + 1] = gB;
#pragma unroll
        for (int e = 0; e < 4; e++) {
            float thr = (noisy[e] > t2) ? t2 : t1;
            float z = (clean[e] - thr) / stdv[e];
            prob[e] = 0.5f * erfcf(-z * 0.70710678118654752f);
        }
    }
#pragma unroll
    for (int off = 16; off > 0; off >>= 1) {
#pragma unroll
        for (int e = 0; e < 4; e++) {
            prob[e]  += __shfl_down_sync(0xffffffffu, prob[e], off);
            gates[e] += __shfl_down_sync(0xffffffffu, gates[e], off);
        }
    }
    if (lane == 0) {
        float loss = (cv2_4(gates[0], gates[1], gates[2], gates[3]) +
                      cv2_4(prob[0], prob[1], prob[2], prob[3])) * 0.01f;
        if (out_size > B * HW) out[B * HW] = loss;
    }
}

// ---------------- K4: fused sparse expert convs ---------------------------
// 288 threads, 4 blocks/SM (<=56 regs). conv1 task per thread = (oc, row),
// processed as TWO sequential 9-wide halves (acc[9] keeps live regs small,
// no spills). conv2 task (cy, cicl) fixed per thread; partial row lives in
// registers across all 8 chunk-slots (gate-pre-scaled w2). 'part' overlays
// hs at the end. smem 44.4KB/block.
#define TDIM 16
#define NTHR 288
#define XW   21    // padded x row stride (odd -> conflict-free)
#define HWID 19    // padded h row stride (odd)
#define PICL 274   // part icl-stride; 16*274 = 4384 <= 5472 (fits in hs)

__global__ void __launch_bounds__(NTHR, 4)
k_expert(const float* __restrict__ x,
         const float* __restrict__ ew1, const float* __restrict__ eb1,
         const float* __restrict__ ew2, const float* __restrict__ eb2,
         float* __restrict__ out) {
    const int b = blockIdx.z, tY = blockIdx.y, tX = blockIdx.x;
    const int tid = threadIdx.x;

    __shared__ float xs[3 * 20 * XW];     // 5040 f
    __shared__ float hs[16 * 18 * HWID];  // 5472 f (reused as 'part')
    __shared__ float w1s[16 * 27];
    __shared__ float w2s[16 * 9];
    __shared__ float b1s[16];

    // load x tile (+halo 2), shared by both experts
    const int gy0 = tY * TDIM - 2, gx0 = tX * TDIM - 2;
    for (int i = tid; i < 3 * 20 * 20; i += NTHR) {
        int c = i / 400, r = (i / 20) % 20, col = i % 20;
        int gy = gy0 + r, gx = gx0 + col;
        float v = 0.f;
        if ((unsigned)gy < 256u && (unsigned)gx < 256u)
            v = x[((size_t)(b * 3 + c) << 16) + (gy << 8) + gx];
        xs[(c * 20 + r) * XW + col] = v;
    }

    const bool interior = (tY > 0) && (tY < H / TDIM - 1) &&
                          (tX > 0) && (tX < W / TDIM - 1);

    const int c1_ocl = tid / 18, c1_yy = tid % 18;   // conv1 task
    const int cy = tid >> 4, cicl = tid & 15;        // conv2 task (tid<256)
    const bool rowok = interior ||
        (unsigned)(tY * TDIM + c1_yy - 1) < (unsigned)H;

    const int   eA = g_eidx[b * 2 + 0], eB = g_eidx[b * 2 + 1];
    const float gA = g_gate[b * 2 + 0], gB = g_gate[b * 2 + 1];

    float acc2[16];  // conv2 partial row, accumulated across chunks+experts
#pragma unroll
    for (int j = 0; j < 16; j++) acc2[j] = 0.f;

    for (int it = 0; it < 8; it++) {
        const int e   = (it < 4) ? eA : eB;
        const float g = (it < 4) ? gA : gB;
        const int ch  = it & 3;

        __syncthreads(); // prior conv2 reads of hs/w2s done (covers xs fill)
        {
            const float* W1 = ew1 + e * (HID * 27) + ch * 432;
            for (int i = tid; i < 432; i += NTHR) w1s[i] = W1[i];
            const float* W2 = ew2 + e * (HID * 9) + ch * 144;
            for (int i = tid; i < 144; i += NTHR) w2s[i] = g * W2[i];
            if (tid < 16) b1s[tid] = eb1[e * HID + ch * 16 + tid];
        }
        __syncthreads();

        // conv1 + ReLU: two 9-wide halves (small live register set)
        {
            const float bias = b1s[c1_ocl];
            float* hrow = &hs[(c1_ocl * 18 + c1_yy) * HWID];
#pragma unroll
            for (int half = 0; half < 2; half++) {
                const int x0 = half * 9;
                float acc[9];
#pragma unroll
                for (int j = 0; j < 9; j++) acc[j] = bias;
#pragma unroll
                for (int ic = 0; ic < 3; ic++) {
#pragma unroll
                    for (int ky = 0; ky < 3; ky++) {
                        const float* row = &xs[(ic * 20 + c1_yy + ky) * XW + x0];
                        const float* wp = &w1s[c1_ocl * 27 + ic * 9 + ky * 3];
                        const float wa = wp[0], wb = wp[1], wc = wp[2];
                        float r0 = row[0], r1 = row[1];
#pragma unroll
                        for (int j = 0; j < 9; j++) {
                            float r2 = row[j + 2];
                            acc[j] += r0 * wa + r1 * wb + r2 * wc;
                            r0 = r1; r1 = r2;
                        }
                    }
                }
                if (interior) {
#pragma unroll
                    for (int j = 0; j < 9; j++) hrow[x0 + j] = fmaxf(acc[j], 0.f);
                } else {
                    // conv2 SAME padding: h == 0 outside the image
#pragma unroll
                    for (int j = 0; j < 9; j++) {
                        const bool ok = rowok &&
                            (unsigned)(tX * TDIM + x0 + j - 1) < (unsigned)W;
                        hrow[x0 + j] = ok ? fmaxf(acc[j], 0.f) : 0.f;
                    }
                }
            }
        }
        __syncthreads();

        // conv2 partial row into registers (task fixed per thread)
        if (tid < 256) {
            const float* wp = &w2s[cicl * 9];
#pragma unroll
            for (int ky = 0; ky < 3; ky++) {
                const float* row = &hs[(cicl * 18 + cy + ky) * HWID];
                const float wa = wp[ky * 3], wb = wp[ky * 3 + 1], wc = wp[ky * 3 + 2];
                float r0 = row[0], r1 = row[1];
#pragma unroll
                for (int j = 0; j < 16; j++) {
                    float r2 = row[j + 2];
                    acc2[j] += r0 * wa + r1 * wb + r2 * wc;
                    r0 = r1; r1 = r2;
                }
            }
        }
    }

    __syncthreads(); // all hs reads done -> overlay part onto hs
    float* part = hs;
    if (tid < 256) {
        float* pp = &part[cicl * PICL + cy * 17];
#pragma unroll
        for (int j = 0; j < 16; j++) pp[j] = acc2[j];
    }
    __syncthreads();

    if (tid < 256) {
        const int oy = tid >> 4, ox = tid & 15;
        float yacc = 0.f;
#pragma unroll
        for (int icl = 0; icl < 16; icl++)
            yacc += part[icl * PICL + oy * 17 + ox];
        yacc += gA * eb2[eA] + gB * eb2[eB];
        out[((size_t)b << 16) + ((tY * TDIM + oy) << 8) + (tX * TDIM + ox)] = yacc;
    }
}

// ---------------- no-op pad launch (keeps k_expert at profile slot 3) ----
__global__ void k_noop() {}

// ---------------- launch ---------------------------------------------------
extern "C" void kernel_launch(void* const* d_in, const int* in_sizes, int n_in,
                              void* d_out, int out_size) {
    const float* x          = (const float*)d_in[0];
    const float* ref        = (const float*)d_in[1];
    const float* noise      = (const float*)d_in[2];
    const float* mod_w1     = (const float*)d_in[3];
    const float* mod_b1     = (const float*)d_in[4];
    const float* mod_w2     = (const float*)d_in[5];
    const float* mod_b2     = (const float*)d_in[6];
    const float* enh_w      = (const float*)d_in[7];
    const float* enh_b      = (const float*)d_in[8];
    const float* fre_prompt = (const float*)d_in[9];
    const float* w_gate     = (const float*)d_in[10];
    const float* w_noise    = (const float*)d_in[11];
    const float* ew1        = (const float*)d_in[12];
    const float* eb1        = (const float*)d_in[13];
    const float* ew2        = (const float*)d_in[14];
    const float* eb2        = (const float*)d_in[15];
    float* out = (float*)d_out;

    k_refsum<<<B * C, 256>>>(ref);                                       // 0
    k_gate_dots<<<B, 512>>>(x, w_gate, w_noise, mod_w1, mod_b1, mod_w2,
                            mod_b2, enh_w, enh_b, fre_prompt);           // 1
    k_finalize<<<1, 32>>>(noise, out, out_size);                         // 2
    k_expert<<<dim3(W / TDIM, H / TDIM, B), NTHR>>>(x, ew1, eb1,
                                                    ew2, eb2, out);      // 3
    k_noop<<<1, 32>>>();                                                 // 4
}

// round 10
// speedup vs baseline: 1.2360x; 1.1668x over previous
#include <cuda_runtime.h>
#include <math.h>

// Problem constants
#define B      16
#define C      3
#define H      256
#define W      256
#define HW     65536      // 256*256
#define D      196608     // C*H*W
#define NEXP   4
#define TOPK   2
#define HID    64
#define FC     6
#define GSLICE 4          // k_gate_dots slices per batch

// ---------------- device scratch (no allocations allowed) ----------------
__device__ float g_refsum[B * C];          // per (b,c) sum over spatial of ref
__device__ float g_part[B * GSLICE * 8];   // gate matvec partials
__device__ float g_gate[B * 2];            // top-2 gate values per batch
__device__ int   g_eidx[B * 2];            // top-2 expert indices per batch

// ---------------- K1: sum ref over spatial per (b,c), float4 loads -------
__global__ void k_refsum(const float* __restrict__ ref) {
    const float4* p = (const float4*)(ref + (size_t)blockIdx.x * HW);
    float s = 0.f;
    for (int i = threadIdx.x; i < HW / 4; i += 256) {
        float4 v = p[i];
        s += (v.x + v.y) + (v.z + v.w);
    }
    __shared__ float sm[256];
    sm[threadIdx.x] = s;
    __syncthreads();
    for (int st = 128; st > 0; st >>= 1) {
        if (threadIdx.x < st) sm[threadIdx.x] += sm[threadIdx.x + st];
        __syncthreads();
    }
    if (threadIdx.x == 0) g_refsum[blockIdx.x] = sm[0];
}

// ---------------- prompt math for one batch (FFT chain collapsed to DC) --
// spatial.mean of irfft2(Z, ortho) == Re(Z[0,0])/256; channel MLPs are
// pointwise in frequency -> only the DC bin matters.
__device__ void prompt_scales(int b,
                              const float* __restrict__ mod_w1,
                              const float* __restrict__ mod_b1,
                              const float* __restrict__ mod_w2,
                              const float* __restrict__ mod_b2,
                              const float* __restrict__ enh_w,
                              const float* __restrict__ enh_b,
                              const float* __restrict__ fre_prompt,
                              float* sc /*[3]*/) {
    float s[3];
#pragma unroll
    for (int c = 0; c < 3; c++) s[c] = g_refsum[b * 3 + c] * (1.f / 256.f);
    float p[12];
#pragma unroll
    for (int i = 0; i < 12; i++) {
        int ci = (i < 6) ? i : i - 6;
        p[i] = (ci < 3) ? s[ci] : 0.f;
    }
    float m1[6];
#pragma unroll
    for (int o = 0; o < 6; o++) {
        float a = mod_b1[o];
#pragma unroll
        for (int i = 0; i < 12; i++) a += mod_w1[o * 12 + i] * p[i];
        m1[o] = fmaxf(a, 0.f);
    }
    float m2[6];
#pragma unroll
    for (int o = 0; o < 6; o++) {
        float a = mod_b2[o];
#pragma unroll
        for (int i = 0; i < 6; i++) a += mod_w2[o * 6 + i] * m1[i];
        m2[o] = a;
    }
    float ein[6];
#pragma unroll
    for (int c = 0; c < 6; c++) ein[c] = m2[c] * fre_prompt[c * (H * (W / 2 + 1))];
    float enh[6];
#pragma unroll
    for (int o = 0; o < 6; o++) {
        float a = enh_b[o];
#pragma unroll
        for (int i = 0; i < 6; i++) a += enh_w[o * 6 + i] * ein[i];
        enh[o] = fmaxf(a, 0.f);
    }
    float v0 = enh[0] * (1.f / 256.f);
    float v1 = enh[1] * (1.f / 256.f);
    float v2 = enh[2] * (1.f / 256.f);
    float mx = fmaxf(v0, fmaxf(v1, v2));
    float e0 = expf(v0 - mx), e1 = expf(v1 - mx), e2 = expf(v2 - mx);
    float inv = 1.f / (e0 + e1 + e2);
    sc[0] = 1.f + e0 * inv;
    sc[1] = 1.f + e1 * inv;
    sc[2] = 1.f + e2 * inv;
}

// ---------------- K2: gating matvecs, grid (B, GSLICE) -------------------
__global__ void k_gate_dots(const float* __restrict__ x,
                            const float* __restrict__ w_gate,
                            const float* __restrict__ w_noise,
                            const float* __restrict__ mod_w1,
                            const float* __restrict__ mod_b1,
                            const float* __restrict__ mod_w2,
                            const float* __restrict__ mod_b2,
                            const float* __restrict__ enh_w,
                            const float* __restrict__ enh_b,
                            const float* __restrict__ fre_prompt) {
    const int b = blockIdx.x, sl = blockIdx.y;
    const int tid = threadIdx.x;
    __shared__ float s_sc[3];
    if (tid == 0) {
        float sc[3];
        prompt_scales(b, mod_w1, mod_b1, mod_w2, mod_b2, enh_w, enh_b,
                      fre_prompt, sc);
        s_sc[0] = sc[0]; s_sc[1] = sc[1]; s_sc[2] = sc[2];
    }
    __syncthreads();
    const float sc0 = s_sc[0], sc1 = s_sc[1], sc2 = s_sc[2];
    const float* xb = x + (size_t)b * D;
    float a[8] = {0, 0, 0, 0, 0, 0, 0, 0};
    const float4* wg4 = (const float4*)w_gate;
    const float4* wn4 = (const float4*)w_noise;
    const int i0 = sl * (D / GSLICE), i1 = i0 + D / GSLICE;
    for (int i = i0 + tid; i < i1; i += 512) {
        float sc = (i < HW) ? sc0 : ((i < 2 * HW) ? sc1 : sc2);
        float xv = xb[i] * sc;
        float4 wg = wg4[i];
        float4 wn = wn4[i];
        a[0] += xv * wg.x; a[1] += xv * wg.y; a[2] += xv * wg.z; a[3] += xv * wg.w;
        a[4] += xv * wn.x; a[5] += xv * wn.y; a[6] += xv * wn.z; a[7] += xv * wn.w;
    }
    __shared__ float sm[512 * 8];
#pragma unroll
    for (int k = 0; k < 8; k++) sm[tid * 8 + k] = a[k];
    __syncthreads();
    for (int st = 256; st > 0; st >>= 1) {
        if (tid < st) {
#pragma unroll
            for (int k = 0; k < 8; k++) sm[tid * 8 + k] += sm[(tid + st) * 8 + k];
        }
        __syncthreads();
    }
    if (tid == 0) {
#pragma unroll
        for (int k = 0; k < 8; k++)
            g_part[(b * GSLICE + sl) * 8 + k] = sm[k];
    }
}

// ---------------- K3: noisy top-k gating + load-balance loss -------------
__device__ __forceinline__ float cv2_4(float a, float b, float c, float d) {
    float m = (a + b + c + d) * 0.25f;
    float va = a - m, vb = b - m, vc = c - m, vd = d - m;
    float var = (va * va + vb * vb + vc * vc + vd * vd) * (1.f / 3.f);
    return var / (m * m + 1e-10f);
}

__global__ void k_finalize(const float* __restrict__ noise,
                           float* __restrict__ out, int out_size) {
    const int lane = threadIdx.x;
    float prob[4] = {0, 0, 0, 0};
    float gates[4] = {0, 0, 0, 0};
    if (lane < B) {
        const int b = lane;
        float lg[8];
#pragma unroll
        for (int k = 0; k < 8; k++) {
            float s = 0.f;
#pragma unroll
            for (int sl = 0; sl < GSLICE; sl++)
                s += g_part[(b * GSLICE + sl) * 8 + k];
            lg[k] = s;
        }
        float clean[4], stdv[4], noisy[4];
#pragma unroll
        for (int e = 0; e < 4; e++) {
            clean[e] = lg[e];
            float z = lg[4 + e];
            float sp = (z > 0.f) ? (z + log1pf(expf(-z))) : log1pf(expf(z));
            stdv[e] = sp + 0.01f;
            noisy[e] = clean[e] + noise[b * 4 + e] * stdv[e];
        }
        float v[4] = {noisy[0], noisy[1], noisy[2], noisy[3]};
        int idx[4] = {0, 1, 2, 3};
#pragma unroll
        for (int s = 0; s < 3; s++) {
            int m = s;
#pragma unroll
            for (int j = s + 1; j < 4; j++)
                if (v[j] > v[m]) m = j;
            float tv = v[s]; v[s] = v[m]; v[m] = tv;
            int ti = idx[s]; idx[s] = idx[m]; idx[m] = ti;
        }
        float t1 = v[1], t2 = v[2];
        float mx = fmaxf(v[0], v[1]);
        float e0 = expf(v[0] - mx), e1 = expf(v[1] - mx);
        float inv = 1.f / (e0 + e1);
        float gA = e0 * inv, gB = e1 * inv;
        gates[idx[0]] = gA;
        gates[idx[1]] = gB;
        g_eidx[b * 2 + 0] = idx[0];
        g_eidx[b * 2 + 1] = idx[1];
        g_gate[b * 2 + 0] = gA;
        g_gate[b * 2 + 1] = gB;
#pragma unroll
        for (int e = 0; e < 4; e++) {
            float thr = (noisy[e] > t2) ? t2 : t1;
            float z = (clean[e] - thr) / stdv[e];
            prob[e] = 0.5f * erfcf(-z * 0.70710678118654752f);
        }
    }
#pragma unroll
    for (int off = 16; off > 0; off >>= 1) {
#pragma unroll
        for (int e = 0; e < 4; e++) {
            prob[e]  += __shfl_down_sync(0xffffffffu, prob[e], off);
            gates[e] += __shfl_down_sync(0xffffffffu, gates[e], off);
        }
    }
    if (lane == 0) {
        float loss = (cv2_4(gates[0], gates[1], gates[2], gates[3]) +
                      cv2_4(prob[0], prob[1], prob[2], prob[3])) * 0.01f;
        if (out_size > B * HW) out[B * HW] = loss;
    }
}

// ---------------- K4: fused sparse expert convs ---------------------------
// 288 threads, 4 blocks/SM. conv1 task = (oc-PAIR, half, row): each thread
// computes TWO output channels over a 9-wide half-row, sharing the x sliding
// window (x-LDS per thread halves vs one-oc scheme). conv2 task (cy, cicl)
// fixed per thread; partial row accumulates in registers across all 8
// chunk-slots (gate-pre-scaled w2). 'part' overlays hs at the end.
#define TDIM 16
#define NTHR 288
#define XW   21    // padded x row stride (odd -> conflict-free)
#define HWID 19    // padded h row stride (odd)
#define PICL 274   // part icl-stride; 16*274 = 4384 <= 5472 (fits in hs)

__global__ void __launch_bounds__(NTHR, 4)
k_expert(const float* __restrict__ x,
         const float* __restrict__ ew1, const float* __restrict__ eb1,
         const float* __restrict__ ew2, const float* __restrict__ eb2,
         float* __restrict__ out) {
    const int b = blockIdx.z, tY = blockIdx.y, tX = blockIdx.x;
    const int tid = threadIdx.x;

    __shared__ float xs[3 * 20 * XW];     // 5040 f
    __shared__ float hs[16 * 18 * HWID];  // 5472 f (reused as 'part')
    __shared__ float w1s[16 * 27];
    __shared__ float w2s[16 * 9];
    __shared__ float b1s[16];

    // load x tile (+halo 2), shared by both experts
    const int gy0 = tY * TDIM - 2, gx0 = tX * TDIM - 2;
    for (int i = tid; i < 3 * 20 * 20; i += NTHR) {
        int c = i / 400, r = (i / 20) % 20, col = i % 20;
        int gy = gy0 + r, gx = gx0 + col;
        float v = 0.f;
        if ((unsigned)gy < 256u && (unsigned)gx < 256u)
            v = x[((size_t)(b * 3 + c) << 16) + (gy << 8) + gx];
        xs[(c * 20 + r) * XW + col] = v;
    }

    const bool interior = (tY > 0) && (tY < H / TDIM - 1) &&
                          (tX > 0) && (tX < W / TDIM - 1);

    // conv1 task: (oc-pair, half, row). 8*2*18 = 288 tasks.
    const int c1_ocp  = tid / 36;            // 0..7 -> ocs {2p, 2p+1}
    const int c1_rem  = tid % 36;
    const int c1_half = c1_rem / 18;         // 0..1
    const int c1_yy   = c1_rem % 18;         // 0..17
    const int c1_x0   = c1_half * 9;
    const int oc0 = 2 * c1_ocp, oc1 = oc0 + 1;
    const bool rowok = interior ||
        (unsigned)(tY * TDIM + c1_yy - 1) < (unsigned)H;

    const int cy = tid >> 4, cicl = tid & 15;   // conv2 task (tid < 256)

    const int   eA = g_eidx[b * 2 + 0], eB = g_eidx[b * 2 + 1];
    const float gA = g_gate[b * 2 + 0], gB = g_gate[b * 2 + 1];

    float acc2[16];  // conv2 partial row, accumulated across chunks+experts
#pragma unroll
    for (int j = 0; j < 16; j++) acc2[j] = 0.f;

    for (int it = 0; it < 8; it++) {
        const int e   = (it < 4) ? eA : eB;
        const float g = (it < 4) ? gA : gB;
        const int ch  = it & 3;

        __syncthreads(); // prior conv2 reads of hs/w2s done (covers xs fill)
        {
            const float* W1 = ew1 + e * (HID * 27) + ch * 432;
            for (int i = tid; i < 432; i += NTHR) w1s[i] = W1[i];
            const float* W2 = ew2 + e * (HID * 9) + ch * 144;
            for (int i = tid; i < 144; i += NTHR) w2s[i] = g * W2[i];
            if (tid < 16) b1s[tid] = eb1[e * HID + ch * 16 + tid];
        }
        __syncthreads();

        // conv1 + ReLU: 2 ocs x 9-wide half-row, shared x sliding window
        {
            float a0[9], a1[9];
            const float b0 = b1s[oc0], b1 = b1s[oc1];
#pragma unroll
            for (int j = 0; j < 9; j++) { a0[j] = b0; a1[j] = b1; }
#pragma unroll
            for (int ic = 0; ic < 3; ic++) {
#pragma unroll
                for (int ky = 0; ky < 3; ky++) {
                    const float* row = &xs[(ic * 20 + c1_yy + ky) * XW + c1_x0];
                    const float* w0 = &w1s[oc0 * 27 + ic * 9 + ky * 3];
                    const float* w1 = &w1s[oc1 * 27 + ic * 9 + ky * 3];
                    const float w0a = w0[0], w0b = w0[1], w0c = w0[2];
                    const float w1a = w1[0], w1b = w1[1], w1c = w1[2];
                    float r0 = row[0], r1 = row[1];
#pragma unroll
                    for (int j = 0; j < 9; j++) {
                        float r2 = row[j + 2];
                        a0[j] += r0 * w0a + r1 * w0b + r2 * w0c;
                        a1[j] += r0 * w1a + r1 * w1b + r2 * w1c;
                        r0 = r1; r1 = r2;
                    }
                }
            }
            float* h0 = &hs[(oc0 * 18 + c1_yy) * HWID + c1_x0];
            float* h1 = &hs[(oc1 * 18 + c1_yy) * HWID + c1_x0];
            if (interior) {
#pragma unroll
                for (int j = 0; j < 9; j++) {
                    h0[j] = fmaxf(a0[j], 0.f);
                    h1[j] = fmaxf(a1[j], 0.f);
                }
            } else {
                // conv2 SAME padding: h == 0 outside the image
#pragma unroll
                for (int j = 0; j < 9; j++) {
                    const bool ok = rowok &&
                        (unsigned)(tX * TDIM + c1_x0 + j - 1) < (unsigned)W;
                    h0[j] = ok ? fmaxf(a0[j], 0.f) : 0.f;
                    h1[j] = ok ? fmaxf(a1[j], 0.f) : 0.f;
                }
            }
        }
        __syncthreads();

        // conv2 partial row into registers (task fixed per thread)
        if (tid < 256) {
            const float* wp = &w2s[cicl * 9];
#pragma unroll
            for (int ky = 0; ky < 3; ky++) {
                const float* row = &hs[(cicl * 18 + cy + ky) * HWID];
                const float wa = wp[ky * 3], wb = wp[ky * 3 + 1], wc = wp[ky * 3 + 2];
                float r0 = row[0], r1 = row[1];
#pragma unroll
                for (int j = 0; j < 16; j++) {
                    float r2 = row[j + 2];
                    acc2[j] += r0 * wa + r1 * wb + r2 * wc;
                    r0 = r1; r1 = r2;
                }
            }
        }
    }

    __syncthreads(); // all hs reads done -> overlay part onto hs
    float* part = hs;
    if (tid < 256) {
        float* pp = &part[cicl * PICL + cy * 17];
#pragma unroll
        for (int j = 0; j < 16; j++) pp[j] = acc2[j];
    }
    __syncthreads();

    if (tid < 256) {
        const int oy = tid >> 4, ox = tid & 15;
        float yacc = 0.f;
#pragma unroll
        for (int icl = 0; icl < 16; icl++)
            yacc += part[icl * PICL + oy * 17 + ox];
        yacc += gA * eb2[eA] + gB * eb2[eB];
        out[((size_t)b << 16) + ((tY * TDIM + oy) << 8) + (tX * TDIM + ox)] = yacc;
    }
}

// ---------------- no-op pad launch (keeps k_expert at profile slot 3) ----
__global__ void k_noop() {}

// ---------------- launch ---------------------------------------------------
extern "C" void kernel_launch(void* const* d_in, const int* in_sizes, int n_in,
                              void* d_out, int out_size) {
    const float* x          = (const float*)d_in[0];
    const float* ref        = (const float*)d_in[1];
    const float* noise      = (const float*)d_in[2];
    const float* mod_w1     = (const float*)d_in[3];
    const float* mod_b1     = (const float*)d_in[4];
    const float* mod_w2     = (const float*)d_in[5];
    const float* mod_b2     = (const float*)d_in[6];
    const float* enh_w      = (const float*)d_in[7];
    const float* enh_b      = (const float*)d_in[8];
    const float* fre_prompt = (const float*)d_in[9];
    const float* w_gate     = (const float*)d_in[10];
    const float* w_noise    = (const float*)d_in[11];
    const float* ew1        = (const float*)d_in[12];
    const float* eb1        = (const float*)d_in[13];
    const float* ew2        = (const float*)d_in[14];
    const float* eb2        = (const float*)d_in[15];
    float* out = (float*)d_out;

    k_refsum<<<B * C, 256>>>(ref);                                       // 0
    k_gate_dots<<<dim3(B, GSLICE), 512>>>(x, w_gate, w_noise, mod_w1,
                                          mod_b1, mod_w2, mod_b2, enh_w,
                                          enh_b, fre_prompt);            // 1
    k_finalize<<<1, 32>>>(noise, out, out_size);                         // 2
    k_expert<<<dim3(W / TDIM, H / TDIM, B), NTHR>>>(x, ew1, eb1,
                                                    ew2, eb2, out);      // 3
    k_noop<<<1, 32>>>();                                                 // 4
}

// round 11
// speedup vs baseline: 1.2754x; 1.0318x over previous
#include <cuda_runtime.h>
#include <math.h>

// Problem constants
#define B      16
#define C      3
#define H      256
#define W      256
#define HW     65536      // 256*256
#define D      196608     // C*H*W
#define NEXP   4
#define TOPK   2
#define HID    64
#define FC     6
#define GSLICE 4          // k_gate_dots slices per batch

// ---------------- device scratch (no allocations allowed) ----------------
__device__ float g_refsum[B * C];          // per (b,c) sum over spatial of ref
__device__ float g_part[B * GSLICE * 8];   // gate matvec partials
__device__ float g_gate[B * 2];            // top-2 gate values per batch
__device__ int   g_eidx[B * 2];            // top-2 expert indices per batch

// ---------------- K1: sum ref over spatial per (b,c), float4 loads -------
__global__ void k_refsum(const float* __restrict__ ref) {
    const float4* p = (const float4*)(ref + (size_t)blockIdx.x * HW);
    float s = 0.f;
    for (int i = threadIdx.x; i < HW / 4; i += 256) {
        float4 v = p[i];
        s += (v.x + v.y) + (v.z + v.w);
    }
    __shared__ float sm[256];
    sm[threadIdx.x] = s;
    __syncthreads();
    for (int st = 128; st > 0; st >>= 1) {
        if (threadIdx.x < st) sm[threadIdx.x] += sm[threadIdx.x + st];
        __syncthreads();
    }
    if (threadIdx.x == 0) g_refsum[blockIdx.x] = sm[0];
}

// ---------------- prompt math for one batch (FFT chain collapsed to DC) --
__device__ void prompt_scales(int b,
                              const float* __restrict__ mod_w1,
                              const float* __restrict__ mod_b1,
                              const float* __restrict__ mod_w2,
                              const float* __restrict__ mod_b2,
                              const float* __restrict__ enh_w,
                              const float* __restrict__ enh_b,
                              const float* __restrict__ fre_prompt,
                              float* sc /*[3]*/) {
    float s[3];
#pragma unroll
    for (int c = 0; c < 3; c++) s[c] = g_refsum[b * 3 + c] * (1.f / 256.f);
    float p[12];
#pragma unroll
    for (int i = 0; i < 12; i++) {
        int ci = (i < 6) ? i : i - 6;
        p[i] = (ci < 3) ? s[ci] : 0.f;
    }
    float m1[6];
#pragma unroll
    for (int o = 0; o < 6; o++) {
        float a = mod_b1[o];
#pragma unroll
        for (int i = 0; i < 12; i++) a += mod_w1[o * 12 + i] * p[i];
        m1[o] = fmaxf(a, 0.f);
    }
    float m2[6];
#pragma unroll
    for (int o = 0; o < 6; o++) {
        float a = mod_b2[o];
#pragma unroll
        for (int i = 0; i < 6; i++) a += mod_w2[o * 6 + i] * m1[i];
        m2[o] = a;
    }
    float ein[6];
#pragma unroll
    for (int c = 0; c < 6; c++) ein[c] = m2[c] * fre_prompt[c * (H * (W / 2 + 1))];
    float enh[6];
#pragma unroll
    for (int o = 0; o < 6; o++) {
        float a = enh_b[o];
#pragma unroll
        for (int i = 0; i < 6; i++) a += enh_w[o * 6 + i] * ein[i];
        enh[o] = fmaxf(a, 0.f);
    }
    float v0 = enh[0] * (1.f / 256.f);
    float v1 = enh[1] * (1.f / 256.f);
    float v2 = enh[2] * (1.f / 256.f);
    float mx = fmaxf(v0, fmaxf(v1, v2));
    float e0 = expf(v0 - mx), e1 = expf(v1 - mx), e2 = expf(v2 - mx);
    float inv = 1.f / (e0 + e1 + e2);
    sc[0] = 1.f + e0 * inv;
    sc[1] = 1.f + e1 * inv;
    sc[2] = 1.f + e2 * inv;
}

// ---------------- K2: gating matvecs, grid (B, GSLICE) -------------------
__global__ void k_gate_dots(const float* __restrict__ x,
                            const float* __restrict__ w_gate,
                            const float* __restrict__ w_noise,
                            const float* __restrict__ mod_w1,
                            const float* __restrict__ mod_b1,
                            const float* __restrict__ mod_w2,
                            const float* __restrict__ mod_b2,
                            const float* __restrict__ enh_w,
                            const float* __restrict__ enh_b,
                            const float* __restrict__ fre_prompt) {
    const int b = blockIdx.x, sl = blockIdx.y;
    const int tid = threadIdx.x;
    __shared__ float s_sc[3];
    if (tid == 0) {
        float sc[3];
        prompt_scales(b, mod_w1, mod_b1, mod_w2, mod_b2, enh_w, enh_b,
                      fre_prompt, sc);
        s_sc[0] = sc[0]; s_sc[1] = sc[1]; s_sc[2] = sc[2];
    }
    __syncthreads();
    const float sc0 = s_sc[0], sc1 = s_sc[1], sc2 = s_sc[2];
    const float* xb = x + (size_t)b * D;
    float a[8] = {0, 0, 0, 0, 0, 0, 0, 0};
    const float4* wg4 = (const float4*)w_gate;
    const float4* wn4 = (const float4*)w_noise;
    const int i0 = sl * (D / GSLICE), i1 = i0 + D / GSLICE;
    for (int i = i0 + tid; i < i1; i += 512) {
        float sc = (i < HW) ? sc0 : ((i < 2 * HW) ? sc1 : sc2);
        float xv = xb[i] * sc;
        float4 wg = wg4[i];
        float4 wn = wn4[i];
        a[0] += xv * wg.x; a[1] += xv * wg.y; a[2] += xv * wg.z; a[3] += xv * wg.w;
        a[4] += xv * wn.x; a[5] += xv * wn.y; a[6] += xv * wn.z; a[7] += xv * wn.w;
    }
    __shared__ float sm[512 * 8];
#pragma unroll
    for (int k = 0; k < 8; k++) sm[tid * 8 + k] = a[k];
    __syncthreads();
    for (int st = 256; st > 0; st >>= 1) {
        if (tid < st) {
#pragma unroll
            for (int k = 0; k < 8; k++) sm[tid * 8 + k] += sm[(tid + st) * 8 + k];
        }
        __syncthreads();
    }
    if (tid == 0) {
#pragma unroll
        for (int k = 0; k < 8; k++)
            g_part[(b * GSLICE + sl) * 8 + k] = sm[k];
    }
}

// ---------------- K3: noisy top-k gating + load-balance loss -------------
__device__ __forceinline__ float cv2_4(float a, float b, float c, float d) {
    float m = (a + b + c + d) * 0.25f;
    float va = a - m, vb = b - m, vc = c - m, vd = d - m;
    float var = (va * va + vb * vb + vc * vc + vd * vd) * (1.f / 3.f);
    return var / (m * m + 1e-10f);
}

__global__ void k_finalize(const float* __restrict__ noise,
                           float* __restrict__ out, int out_size) {
    const int lane = threadIdx.x;
    float prob[4] = {0, 0, 0, 0};
    float gates[4] = {0, 0, 0, 0};
    if (lane < B) {
        const int b = lane;
        float lg[8];
#pragma unroll
        for (int k = 0; k < 8; k++) {
            float s = 0.f;
#pragma unroll
            for (int sl = 0; sl < GSLICE; sl++)
                s += g_part[(b * GSLICE + sl) * 8 + k];
            lg[k] = s;
        }
        float clean[4], stdv[4], noisy[4];
#pragma unroll
        for (int e = 0; e < 4; e++) {
            clean[e] = lg[e];
            float z = lg[4 + e];
            float sp = (z > 0.f) ? (z + log1pf(expf(-z))) : log1pf(expf(z));
            stdv[e] = sp + 0.01f;
            noisy[e] = clean[e] + noise[b * 4 + e] * stdv[e];
        }
        float v[4] = {noisy[0], noisy[1], noisy[2], noisy[3]};
        int idx[4] = {0, 1, 2, 3};
#pragma unroll
        for (int s = 0; s < 3; s++) {
            int m = s;
#pragma unroll
            for (int j = s + 1; j < 4; j++)
                if (v[j] > v[m]) m = j;
            float tv = v[s]; v[s] = v[m]; v[m] = tv;
            int ti = idx[s]; idx[s] = idx[m]; idx[m] = ti;
        }
        float t1 = v[1], t2 = v[2];
        float mx = fmaxf(v[0], v[1]);
        float e0 = expf(v[0] - mx), e1 = expf(v[1] - mx);
        float inv = 1.f / (e0 + e1);
        float gA = e0 * inv, gB = e1 * inv;
        gates[idx[0]] = gA;
        gates[idx[1]] = gB;
        g_eidx[b * 2 + 0] = idx[0];
        g_eidx[b * 2 + 1] = idx[1];
        g_gate[b * 2 + 0] = gA;
        g_gate[b * 2 + 1] = gB;
#pragma unroll
        for (int e = 0; e < 4; e++) {
            float thr = (noisy[e] > t2) ? t2 : t1;
            float z = (clean[e] - thr) / stdv[e];
            prob[e] = 0.5f * erfcf(-z * 0.70710678118654752f);
        }
    }
#pragma unroll
    for (int off = 16; off > 0; off >>= 1) {
#pragma unroll
        for (int e = 0; e < 4; e++) {
            prob[e]  += __shfl_down_sync(0xffffffffu, prob[e], off);
            gates[e] += __shfl_down_sync(0xffffffffu, gates[e], off);
        }
    }
    if (lane == 0) {
        float loss = (cv2_4(gates[0], gates[1], gates[2], gates[3]) +
                      cv2_4(prob[0], prob[1], prob[2], prob[3])) * 0.01f;
        if (out_size > B * HW) out[B * HW] = loss;
    }
}

// ---------------- K4: fused sparse expert convs ---------------------------
// 288 threads, 3 blocks/SM. Chunk = 32 output channels (4 iterations total:
// 2 experts x 2 chunks). conv1 task = (oc-QUAD, half, row): each thread
// computes FOUR output channels over a 9-wide half-row sharing one x sliding
// window (x-LDS per FMA halves vs 2-oc scheme; barrier rounds halve).
// conv2 folds both channel-halves (cicl, cicl+16) into the same 16 persistent
// accumulator registers. 'part' overlays hs at the end.
#define TDIM 16
#define NTHR 288
#define CHP  32    // channels per chunk
#define XW   21    // padded x row stride (odd -> conflict-free)
#define HWID 19    // padded h row stride (odd)
#define PICL 274   // part icl-stride; 16*274 = 4384 <= 10944 (fits in hs)

__global__ void __launch_bounds__(NTHR, 3)
k_expert(const float* __restrict__ x,
         const float* __restrict__ ew1, const float* __restrict__ eb1,
         const float* __restrict__ ew2, const float* __restrict__ eb2,
         float* __restrict__ out) {
    const int b = blockIdx.z, tY = blockIdx.y, tX = blockIdx.x;
    const int tid = threadIdx.x;

    __shared__ float xs[3 * 20 * XW];      // 5040 f
    __shared__ float hs[CHP * 18 * HWID];  // 10944 f (reused as 'part')
    __shared__ float w1s[CHP * 27];        // 864 f
    __shared__ float w2s[CHP * 9];         // 288 f
    __shared__ float b1s[CHP];

    // load x tile (+halo 2), shared by both experts
    const int gy0 = tY * TDIM - 2, gx0 = tX * TDIM - 2;
    for (int i = tid; i < 3 * 20 * 20; i += NTHR) {
        int c = i / 400, r = (i / 20) % 20, col = i % 20;
        int gy = gy0 + r, gx = gx0 + col;
        float v = 0.f;
        if ((unsigned)gy < 256u && (unsigned)gx < 256u)
            v = x[((size_t)(b * 3 + c) << 16) + (gy << 8) + gx];
        xs[(c * 20 + r) * XW + col] = v;
    }

    const bool interior = (tY > 0) && (tY < H / TDIM - 1) &&
                          (tX > 0) && (tX < W / TDIM - 1);

    // conv1 task: (oc-quad, half, row). 8*2*18 = 288 tasks.
    const int c1_ocq  = tid / 36;            // 0..7 -> ocs {4q .. 4q+3}
    const int c1_rem  = tid % 36;
    const int c1_half = c1_rem / 18;         // 0..1
    const int c1_yy   = c1_rem % 18;         // 0..17
    const int c1_x0   = c1_half * 9;
    const int oc0 = 4 * c1_ocq;
    const bool rowok = interior ||
        (unsigned)(tY * TDIM + c1_yy - 1) < (unsigned)H;

    const int cy = tid >> 4, cicl = tid & 15;   // conv2 task (tid < 256)

    const int   eA = g_eidx[b * 2 + 0], eB = g_eidx[b * 2 + 1];
    const float gA = g_gate[b * 2 + 0], gB = g_gate[b * 2 + 1];

    float acc2[16];  // conv2 partial row, accumulated across chunks+experts
#pragma unroll
    for (int j = 0; j < 16; j++) acc2[j] = 0.f;

    for (int it = 0; it < 4; it++) {
        const int e   = (it < 2) ? eA : eB;
        const float g = (it < 2) ? gA : gB;
        const int ch  = it & 1;               // chunk half (32 channels)

        __syncthreads(); // prior conv2 reads of hs/w2s done (covers xs fill)
        {
            const float* W1 = ew1 + e * (HID * 27) + ch * (CHP * 27);
            for (int i = tid; i < CHP * 27; i += NTHR) w1s[i] = W1[i];
            const float* W2 = ew2 + e * (HID * 9) + ch * (CHP * 9);
            for (int i = tid; i < CHP * 9; i += NTHR) w2s[i] = g * W2[i];
            if (tid < CHP) b1s[tid] = eb1[e * HID + ch * CHP + tid];
        }
        __syncthreads();

        // conv1 + ReLU: 4 ocs x 9-wide half-row, shared x sliding window
        {
            float a0[9], a1[9], a2[9], a3[9];
            {
                const float bb0 = b1s[oc0], bb1 = b1s[oc0 + 1];
                const float bb2 = b1s[oc0 + 2], bb3 = b1s[oc0 + 3];
#pragma unroll
                for (int j = 0; j < 9; j++) {
                    a0[j] = bb0; a1[j] = bb1; a2[j] = bb2; a3[j] = bb3;
                }
            }
#pragma unroll
            for (int ic = 0; ic < 3; ic++) {
#pragma unroll
                for (int ky = 0; ky < 3; ky++) {
                    const float* row = &xs[(ic * 20 + c1_yy + ky) * XW + c1_x0];
                    const int wb0 = oc0 * 27 + ic * 9 + ky * 3;
                    const float w0a = w1s[wb0],      w0b = w1s[wb0 + 1],      w0c = w1s[wb0 + 2];
                    const float w1a = w1s[wb0 + 27], w1b = w1s[wb0 + 28],     w1c = w1s[wb0 + 29];
                    const float w2a = w1s[wb0 + 54], w2b = w1s[wb0 + 55],     w2c = w1s[wb0 + 56];
                    const float w3a = w1s[wb0 + 81], w3b = w1s[wb0 + 82],     w3c = w1s[wb0 + 83];
                    float r0 = row[0], r1 = row[1];
#pragma unroll
                    for (int j = 0; j < 9; j++) {
                        float r2 = row[j + 2];
                        a0[j] += r0 * w0a + r1 * w0b + r2 * w0c;
                        a1[j] += r0 * w1a + r1 * w1b + r2 * w1c;
                        a2[j] += r0 * w2a + r1 * w2b + r2 * w2c;
                        a3[j] += r0 * w3a + r1 * w3b + r2 * w3c;
                        r0 = r1; r1 = r2;
                    }
                }
            }
            float* h0 = &hs[((oc0 + 0) * 18 + c1_yy) * HWID + c1_x0];
            float* h1 = &hs[((oc0 + 1) * 18 + c1_yy) * HWID + c1_x0];
            float* h2 = &hs[((oc0 + 2) * 18 + c1_yy) * HWID + c1_x0];
            float* h3 = &hs[((oc0 + 3) * 18 + c1_yy) * HWID + c1_x0];
            if (interior) {
#pragma unroll
                for (int j = 0; j < 9; j++) {
                    h0[j] = fmaxf(a0[j], 0.f);
                    h1[j] = fmaxf(a1[j], 0.f);
                    h2[j] = fmaxf(a2[j], 0.f);
                    h3[j] = fmaxf(a3[j], 0.f);
                }
            } else {
                // conv2 SAME padding: h == 0 outside the image
#pragma unroll
                for (int j = 0; j < 9; j++) {
                    const bool ok = rowok &&
                        (unsigned)(tX * TDIM + c1_x0 + j - 1) < (unsigned)W;
                    h0[j] = ok ? fmaxf(a0[j], 0.f) : 0.f;
                    h1[j] = ok ? fmaxf(a1[j], 0.f) : 0.f;
                    h2[j] = ok ? fmaxf(a2[j], 0.f) : 0.f;
                    h3[j] = ok ? fmaxf(a3[j], 0.f) : 0.f;
                }
            }
        }
        __syncthreads();

        // conv2: both channel-halves fold into the same 16 accumulators
        if (tid < 256) {
#pragma unroll
            for (int cc = 0; cc < 2; cc++) {
                const int c2 = cicl + cc * 16;
                const float* wp = &w2s[c2 * 9];
#pragma unroll
                for (int ky = 0; ky < 3; ky++) {
                    const float* row = &hs[(c2 * 18 + cy + ky) * HWID];
                    const float wa = wp[ky * 3], wb = wp[ky * 3 + 1], wc = wp[ky * 3 + 2];
                    float r0 = row[0], r1 = row[1];
#pragma unroll
                    for (int j = 0; j < 16; j++) {
                        float r2 = row[j + 2];
                        acc2[j] += r0 * wa + r1 * wb + r2 * wc;
                        r0 = r1; r1 = r2;
                    }
                }
            }
        }
    }

    __syncthreads(); // all hs reads done -> overlay part onto hs
    float* part = hs;
    if (tid < 256) {
        float* pp = &part[cicl * PICL + cy * 17];
#pragma unroll
        for (int j = 0; j < 16; j++) pp[j] = acc2[j];
    }
    __syncthreads();

    if (tid < 256) {
        const int oy = tid >> 4, ox = tid & 15;
        float yacc = 0.f;
#pragma unroll
        for (int icl = 0; icl < 16; icl++)
            yacc += part[icl * PICL + oy * 17 + ox];
        yacc += gA * eb2[eA] + gB * eb2[eB];
        out[((size_t)b << 16) + ((tY * TDIM + oy) << 8) + (tX * TDIM + ox)] = yacc;
    }
}

// ---------------- no-op pad launch (keeps k_expert at profile slot 3) ----
__global__ void k_noop() {}

// ---------------- launch ---------------------------------------------------
extern "C" void kernel_launch(void* const* d_in, const int* in_sizes, int n_in,
                              void* d_out, int out_size) {
    const float* x          = (const float*)d_in[0];
    const float* ref        = (const float*)d_in[1];
    const float* noise      = (const float*)d_in[2];
    const float* mod_w1     = (const float*)d_in[3];
    const float* mod_b1     = (const float*)d_in[4];
    const float* mod_w2     = (const float*)d_in[5];
    const float* mod_b2     = (const float*)d_in[6];
    const float* enh_w      = (const float*)d_in[7];
    const float* enh_b      = (const float*)d_in[8];
    const float* fre_prompt = (const float*)d_in[9];
    const float* w_gate     = (const float*)d_in[10];
    const float* w_noise    = (const float*)d_in[11];
    const float* ew1        = (const float*)d_in[12];
    const float* eb1        = (const float*)d_in[13];
    const float* ew2        = (const float*)d_in[14];
    const float* eb2        = (const float*)d_in[15];
    float* out = (float*)d_out;

    k_refsum<<<B * C, 256>>>(ref);                                       // 0
    k_gate_dots<<<dim3(B, GSLICE), 512>>>(x, w_gate, w_noise, mod_w1,
                                          mod_b1, mod_w2, mod_b2, enh_w,
                                          enh_b, fre_prompt);            // 1
    k_finalize<<<1, 32>>>(noise, out, out_size);                         // 2
    k_expert<<<dim3(W / TDIM, H / TDIM, B), NTHR>>>(x, ew1, eb1,
                                                    ew2, eb2, out);      // 3
    k_noop<<<1, 32>>>();                                                 // 4
}

// round 13
// speedup vs baseline: 1.3375x; 1.0487x over previous
#include <cuda_runtime.h>
#include <math.h>

// Problem constants
#define B      16
#define C      3
#define H      256
#define W      256
#define HW     65536
#define D      196608
#define NEXP   4
#define TOPK   2
#define HID    64
#define FC     6
#define GSLICE 4

// ---------------- packed f32x2 helpers (sm_100+) --------------------------
typedef unsigned long long u64;

__device__ __forceinline__ u64 pack2(float lo, float hi) {
    u64 r;
    asm("mov.b64 %0, {%1, %2};" : "=l"(r) : "f"(lo), "f"(hi));
    return r;
}
__device__ __forceinline__ void unpack2(u64 v, float& lo, float& hi) {
    asm("mov.b64 {%0, %1}, %2;" : "=f"(lo), "=f"(hi) : "l"(v));
}
__device__ __forceinline__ void fma2(u64& d, u64 a, u64 b) {
    asm("fma.rn.f32x2 %0, %1, %2, %0;" : "+l"(d) : "l"(a), "l"(b));
}

// ---------------- device scratch ------------------------------------------
__device__ float g_refsum[B * C];
__device__ float g_part[B * GSLICE * 8];
__device__ float g_gate[B * 2];
__device__ int   g_eidx[B * 2];

// ---------------- K1: sum ref over spatial per (b,c) ----------------------
__global__ void k_refsum(const float* __restrict__ ref) {
    const float4* p = (const float4*)(ref + (size_t)blockIdx.x * HW);
    float s = 0.f;
    for (int i = threadIdx.x; i < HW / 4; i += 256) {
        float4 v = p[i];
        s += (v.x + v.y) + (v.z + v.w);
    }
    __shared__ float sm[256];
    sm[threadIdx.x] = s;
    __syncthreads();
    for (int st = 128; st > 0; st >>= 1) {
        if (threadIdx.x < st) sm[threadIdx.x] += sm[threadIdx.x + st];
        __syncthreads();
    }
    if (threadIdx.x == 0) g_refsum[blockIdx.x] = sm[0];
}

// ---------------- prompt math (FFT chain collapsed to DC bin) -------------
__device__ void prompt_scales(int b,
                              const float* __restrict__ mod_w1,
                              const float* __restrict__ mod_b1,
                              const float* __restrict__ mod_w2,
                              const float* __restrict__ mod_b2,
                              const float* __restrict__ enh_w,
                              const float* __restrict__ enh_b,
                              const float* __restrict__ fre_prompt,
                              float* sc) {
    float s[3];
#pragma unroll
    for (int c = 0; c < 3; c++) s[c] = g_refsum[b * 3 + c] * (1.f / 256.f);
    float p[12];
#pragma unroll
    for (int i = 0; i < 12; i++) {
        int ci = (i < 6) ? i : i - 6;
        p[i] = (ci < 3) ? s[ci] : 0.f;
    }
    float m1[6];
#pragma unroll
    for (int o = 0; o < 6; o++) {
        float a = mod_b1[o];
#pragma unroll
        for (int i = 0; i < 12; i++) a += mod_w1[o * 12 + i] * p[i];
        m1[o] = fmaxf(a, 0.f);
    }
    float m2[6];
#pragma unroll
    for (int o = 0; o < 6; o++) {
        float a = mod_b2[o];
#pragma unroll
        for (int i = 0; i < 6; i++) a += mod_w2[o * 6 + i] * m1[i];
        m2[o] = a;
    }
    float ein[6];
#pragma unroll
    for (int c = 0; c < 6; c++) ein[c] = m2[c] * fre_prompt[c * (H * (W / 2 + 1))];
    float enh[6];
#pragma unroll
    for (int o = 0; o < 6; o++) {
        float a = enh_b[o];
#pragma unroll
        for (int i = 0; i < 6; i++) a += enh_w[o * 6 + i] * ein[i];
        enh[o] = fmaxf(a, 0.f);
    }
    float v0 = enh[0] * (1.f / 256.f);
    float v1 = enh[1] * (1.f / 256.f);
    float v2 = enh[2] * (1.f / 256.f);
    float mx = fmaxf(v0, fmaxf(v1, v2));
    float e0 = expf(v0 - mx), e1 = expf(v1 - mx), e2 = expf(v2 - mx);
    float inv = 1.f / (e0 + e1 + e2);
    sc[0] = 1.f + e0 * inv;
    sc[1] = 1.f + e1 * inv;
    sc[2] = 1.f + e2 * inv;
}

// ---------------- K2: gating matvecs, grid (B, GSLICE) --------------------
__global__ void k_gate_dots(const float* __restrict__ x,
                            const float* __restrict__ w_gate,
                            const float* __restrict__ w_noise,
                            const float* __restrict__ mod_w1,
                            const float* __restrict__ mod_b1,
                            const float* __restrict__ mod_w2,
                            const float* __restrict__ mod_b2,
                            const float* __restrict__ enh_w,
                            const float* __restrict__ enh_b,
                            const float* __restrict__ fre_prompt) {
    const int b = blockIdx.x, sl = blockIdx.y;
    const int tid = threadIdx.x;
    __shared__ float s_sc[3];
    if (tid == 0) {
        float sc[3];
        prompt_scales(b, mod_w1, mod_b1, mod_w2, mod_b2, enh_w, enh_b,
                      fre_prompt, sc);
        s_sc[0] = sc[0]; s_sc[1] = sc[1]; s_sc[2] = sc[2];
    }
    __syncthreads();
    const float sc0 = s_sc[0], sc1 = s_sc[1], sc2 = s_sc[2];
    const float* xb = x + (size_t)b * D;
    float a[8] = {0, 0, 0, 0, 0, 0, 0, 0};
    const float4* wg4 = (const float4*)w_gate;
    const float4* wn4 = (const float4*)w_noise;
    const int i0 = sl * (D / GSLICE), i1 = i0 + D / GSLICE;
    for (int i = i0 + tid; i < i1; i += 512) {
        float sc = (i < HW) ? sc0 : ((i < 2 * HW) ? sc1 : sc2);
        float xv = xb[i] * sc;
        float4 wg = wg4[i];
        float4 wn = wn4[i];
        a[0] += xv * wg.x; a[1] += xv * wg.y; a[2] += xv * wg.z; a[3] += xv * wg.w;
        a[4] += xv * wn.x; a[5] += xv * wn.y; a[6] += xv * wn.z; a[7] += xv * wn.w;
    }
    __shared__ float sm[512 * 8];
#pragma unroll
    for (int k = 0; k < 8; k++) sm[tid * 8 + k] = a[k];
    __syncthreads();
    for (int st = 256; st > 0; st >>= 1) {
        if (tid < st) {
#pragma unroll
            for (int k = 0; k < 8; k++) sm[tid * 8 + k] += sm[(tid + st) * 8 + k];
        }
        __syncthreads();
    }
    if (tid == 0) {
#pragma unroll
        for (int k = 0; k < 8; k++)
            g_part[(b * GSLICE + sl) * 8 + k] = sm[k];
    }
}

// ---------------- K3: noisy top-k gating + load-balance loss --------------
__device__ __forceinline__ float cv2_4(float a, float b, float c, float d) {
    float m = (a + b + c + d) * 0.25f;
    float va = a - m, vb = b - m, vc = c - m, vd = d - m;
    float var = (va * va + vb * vb + vc * vc + vd * vd) * (1.f / 3.f);
    return var / (m * m + 1e-10f);
}

__global__ void k_finalize(const float* __restrict__ noise,
                           float* __restrict__ out, int out_size) {
    const int lane = threadIdx.x;
    float prob[4] = {0, 0, 0, 0};
    float gates[4] = {0, 0, 0, 0};
    if (lane < B) {
        const int b = lane;
        float lg[8];
#pragma unroll
        for (int k = 0; k < 8; k++) {
            float s = 0.f;
#pragma unroll
            for (int sl = 0; sl < GSLICE; sl++)
                s += g_part[(b * GSLICE + sl) * 8 + k];
            lg[k] = s;
        }
        float clean[4], stdv[4], noisy[4];
#pragma unroll
        for (int e = 0; e < 4; e++) {
            clean[e] = lg[e];
            float z = lg[4 + e];
            float sp = (z > 0.f) ? (z + log1pf(expf(-z))) : log1pf(expf(z));
            stdv[e] = sp + 0.01f;
            noisy[e] = clean[e] + noise[b * 4 + e] * stdv[e];
        }
        float v[4] = {noisy[0], noisy[1], noisy[2], noisy[3]};
        int idx[4] = {0, 1, 2, 3};
#pragma unroll
        for (int s = 0; s < 3; s++) {
            int m = s;
#pragma unroll
            for (int j = s + 1; j < 4; j++)
                if (v[j] > v[m]) m = j;
            float tv = v[s]; v[s] = v[m]; v[m] = tv;
            int ti = idx[s]; idx[s] = idx[m]; idx[m] = ti;
        }
        float t1 = v[1], t2 = v[2];
        float mx = fmaxf(v[0], v[1]);
        float e0 = expf(v[0] - mx), e1 = expf(v[1] - mx);
        float inv = 1.f / (e0 + e1);
        float gA = e0 * inv, gB = e1 * inv;
        gates[idx[0]] = gA;
        gates[idx[1]] = gB;
        g_eidx[b * 2 + 0] = idx[0];
        g_eidx[b * 2 + 1] = idx[1];
        g_gate[b * 2 + 0] = gA;
        g_gate[b * 2 + 1] = gB;
#pragma unroll
        for (int e = 0; e < 4; e++) {
            float thr = (noisy[e] > t2) ? t2 : t1;
            float z = (clean[e] - thr) / stdv[e];
            prob[e] = 0.5f * erfcf(-z * 0.70710678118654752f);
        }
    }
#pragma unroll
    for (int off = 16; off > 0; off >>= 1) {
#pragma unroll
        for (int e = 0; e < 4; e++) {
            prob[e]  += __shfl_down_sync(0xffffffffu, prob[e], off);
            gates[e] += __shfl_down_sync(0xffffffffu, gates[e], off);
        }
    }
    if (lane == 0) {
        float loss = (cv2_4(gates[0], gates[1], gates[2], gates[3]) +
                      cv2_4(prob[0], prob[1], prob[2], prob[3])) * 0.01f;
        if (out_size > B * HW) out[B * HW] = loss;
    }
}

// ---------------- K4: fused sparse expert convs (packed f32x2) ------------
// 288 threads, 3 blocks/SM. Chunk = 32 channels = 16 channel-PAIRS.
// conv1 task = (pair, row): 16x18 = 288. Each fma.rn.f32x2 computes both
// channels of the pair (x broadcast-packed, weights pre-packed in smem).
// h stored channel-interleaved (float2) -> conv2 reads pairs with LDS.64,
// lane-split accumulation folded into persistent scalar acc2[16] per iter.
#define TDIM 16
#define NTHR 288
#define CHP  32
#define XW   21          // xs row stride (floats, odd)
#define HP2  343         // hs2 per-pair block stride in u64 (18*19+1 skew)
#define PICL 274

__global__ void __launch_bounds__(NTHR, 3)
k_expert(const float* __restrict__ x,
         const float* __restrict__ ew1, const float* __restrict__ eb1,
         const float* __restrict__ ew2, const float* __restrict__ eb2,
         float* __restrict__ out) {
    const int b = blockIdx.z, tY = blockIdx.y, tX = blockIdx.x;
    const int tid = threadIdx.x;

    __shared__ float xs[3 * 20 * XW];     // 20160 B
    __shared__ u64   hs2[16 * HP2];       // 43904 B (reused as 'part')
    __shared__ u64   w1p[16 * 27];        // 3456 B  (packed ch-pairs)
    __shared__ u64   w2p[16 * 9];         // 1152 B  (packed, gate-scaled)
    __shared__ float b1s[CHP];

    // load x tile (+halo 2), shared by both experts
    const int gy0 = tY * TDIM - 2, gx0 = tX * TDIM - 2;
    for (int i = tid; i < 3 * 20 * 20; i += NTHR) {
        int c = i / 400, r = (i / 20) % 20, col = i % 20;
        int gy = gy0 + r, gx = gx0 + col;
        float v = 0.f;
        if ((unsigned)gy < 256u && (unsigned)gx < 256u)
            v = x[((size_t)(b * 3 + c) << 16) + (gy << 8) + gx];
        xs[(c * 20 + r) * XW + col] = v;
    }

    const bool interior = (tY > 0) && (tY < H / TDIM - 1) &&
                          (tX > 0) && (tX < W / TDIM - 1);

    // conv1 task: (pair, row)
    const int c1_p  = tid / 18;          // 0..15
    const int c1_yy = tid % 18;          // 0..17
    const bool rowok = interior ||
        (unsigned)(tY * TDIM + c1_yy - 1) < (unsigned)H;

    const int cy = tid >> 4, cp = tid & 15;   // conv2 task (tid < 256)

    const int   eA = g_eidx[b * 2 + 0], eB = g_eidx[b * 2 + 1];
    const float gA = g_gate[b * 2 + 0], gB = g_gate[b * 2 + 1];

    float acc2[16];
#pragma unroll
    for (int j = 0; j < 16; j++) acc2[j] = 0.f;

    for (int it = 0; it < 4; it++) {
        const int e   = (it < 2) ? eA : eB;
        const float g = (it < 2) ? gA : gB;
        const int ch  = it & 1;

        __syncthreads(); // prior conv2 reads of hs2/w2p done (covers xs fill)
        {
            const float* W1 = ew1 + e * (HID * 27) + ch * (CHP * 27);
            for (int i = tid; i < 16 * 27; i += NTHR) {
                int p = i / 27, k = i % 27;
                w1p[i] = pack2(W1[(2 * p) * 27 + k], W1[(2 * p + 1) * 27 + k]);
            }
            const float* W2 = ew2 + e * (HID * 9) + ch * (CHP * 9);
            for (int i = tid; i < 16 * 9; i += NTHR) {
                int p = i / 9, k = i % 9;
                w2p[i] = pack2(g * W2[(2 * p) * 9 + k], g * W2[(2 * p + 1) * 9 + k]);
            }
            if (tid < CHP) b1s[tid] = eb1[e * HID + ch * CHP + tid];
        }
        __syncthreads();

        // conv1 + ReLU: channel-pair per thread, 18-wide row in two 9-passes
        {
            const u64 bp = pack2(b1s[2 * c1_p], b1s[2 * c1_p + 1]);
            u64* hrow = &hs2[c1_p * HP2 + c1_yy * 19];
#pragma unroll
            for (int pass = 0; pass < 2; pass++) {
                const int x0 = pass * 9;
                u64 a01[9];
#pragma unroll
                for (int j = 0; j < 9; j++) a01[j] = bp;
#pragma unroll
                for (int ic = 0; ic < 3; ic++) {
#pragma unroll
                    for (int ky = 0; ky < 3; ky++) {
                        const float* row = &xs[(ic * 20 + c1_yy + ky) * XW + x0];
                        const u64* wp = &w1p[c1_p * 27 + ic * 9 + ky * 3];
                        const u64 wa = wp[0], wb = wp[1], wc = wp[2];
                        float r0 = row[0], r1 = row[1];
                        u64 rp0 = pack2(r0, r0), rp1 = pack2(r1, r1);
#pragma unroll
                        for (int j = 0; j < 9; j++) {
                            float r2 = row[j + 2];
                            u64 rp2 = pack2(r2, r2);
                            fma2(a01[j], rp0, wa);
                            fma2(a01[j], rp1, wb);
                            fma2(a01[j], rp2, wc);
                            rp0 = rp1; rp1 = rp2;
                        }
                    }
                }
                if (interior) {
#pragma unroll
                    for (int j = 0; j < 9; j++) {
                        float lo, hi;
                        unpack2(a01[j], lo, hi);
                        hrow[x0 + j] = pack2(fmaxf(lo, 0.f), fmaxf(hi, 0.f));
                    }
                } else {
                    // conv2 SAME padding: h == 0 outside the image
#pragma unroll
                    for (int j = 0; j < 9; j++) {
                        float lo, hi;
                        unpack2(a01[j], lo, hi);
                        const bool ok = rowok &&
                            (unsigned)(tX * TDIM + x0 + j - 1) < (unsigned)W;
                        hrow[x0 + j] = ok ? pack2(fmaxf(lo, 0.f), fmaxf(hi, 0.f))
                                          : 0ull;
                    }
                }
            }
        }
        __syncthreads();

        // conv2: pair cp, sliding window over packed h rows; lane-split
        // partials in accP, folded into scalar acc2 once per iteration.
        if (tid < 256) {
            u64 accP[16];
#pragma unroll
            for (int j = 0; j < 16; j++) accP[j] = 0ull;
            const u64* w2row = &w2p[cp * 9];
            const u64 w0 = w2row[0], w1 = w2row[1], w2 = w2row[2];
            const u64 w3 = w2row[3], w4 = w2row[4], w5 = w2row[5];
            const u64 w6 = w2row[6], w7 = w2row[7], w8 = w2row[8];
#pragma unroll
            for (int ky = 0; ky < 3; ky++) {
                const u64* row = &hs2[cp * HP2 + (cy + ky) * 19];
                const u64 wa = (ky == 0) ? w0 : (ky == 1) ? w3 : w6;
                const u64 wb = (ky == 0) ? w1 : (ky == 1) ? w4 : w7;
                const u64 wc = (ky == 0) ? w2 : (ky == 1) ? w5 : w8;
                u64 rp0 = row[0], rp1 = row[1];
#pragma unroll
                for (int j = 0; j < 16; j++) {
                    u64 rp2 = row[j + 2];
                    fma2(accP[j], rp0, wa);
                    fma2(accP[j], rp1, wb);
                    fma2(accP[j], rp2, wc);
                    rp0 = rp1; rp1 = rp2;
                }
            }
#pragma unroll
            for (int j = 0; j < 16; j++) {
                float lo, hi;
                unpack2(accP[j], lo, hi);
                acc2[j] += lo + hi;
            }
        }
    }

    __syncthreads(); // all hs2 reads done -> overlay part
    float* part = (float*)hs2;
    if (tid < 256) {
        float* pp = &part[cp * PICL + cy * 17];
#pragma unroll
        for (int j = 0; j < 16; j++) pp[j] = acc2[j];
    }
    __syncthreads();

    if (tid < 256) {
        const int oy = tid >> 4, ox = tid & 15;
        float yacc = 0.f;
#pragma unroll
        for (int icl = 0; icl < 16; icl++)
            yacc += part[icl * PICL + oy * 17 + ox];
        yacc += gA * eb2[eA] + gB * eb2[eB];
        out[((size_t)b << 16) + ((tY * TDIM + oy) << 8) + (tX * TDIM + ox)] = yacc;
    }
}

// ---------------- no-op pad launch (keeps k_expert at profile slot 3) ----
__global__ void k_noop() {}

// ---------------- launch ---------------------------------------------------
extern "C" void kernel_launch(void* const* d_in, const int* in_sizes, int n_in,
                              void* d_out, int out_size) {
    const float* x          = (const float*)d_in[0];
    const float* ref        = (const float*)d_in[1];
    const float* noise      = (const float*)d_in[2];
    const float* mod_w1     = (const float*)d_in[3];
    const float* mod_b1     = (const float*)d_in[4];
    const float* mod_w2     = (const float*)d_in[5];
    const float* mod_b2     = (const float*)d_in[6];
    const float* enh_w      = (const float*)d_in[7];
    const float* enh_b      = (const float*)d_in[8];
    const float* fre_prompt = (const float*)d_in[9];
    const float* w_gate     = (const float*)d_in[10];
    const float* w_noise    = (const float*)d_in[11];
    const float* ew1        = (const float*)d_in[12];
    const float* eb1        = (const float*)d_in[13];
    const float* ew2        = (const float*)d_in[14];
    const float* eb2        = (const float*)d_in[15];
    float* out = (float*)d_out;

    k_refsum<<<B * C, 256>>>(ref);                                       // 0
    k_gate_dots<<<dim3(B, GSLICE), 512>>>(x, w_gate, w_noise, mod_w1,
                                          mod_b1, mod_w2, mod_b2, enh_w,
                                          enh_b, fre_prompt);            // 1
    k_finalize<<<1, 32>>>(noise, out, out_size);                         // 2
    k_expert<<<dim3(W / TDIM, H / TDIM, B), NTHR>>>(x, ew1, eb1,
                                                    ew2, eb2, out);      // 3
    k_noop<<<1, 32>>>();                                                 // 4
}

// round 16
// speedup vs baseline: 1.6859x; 1.2605x over previous
#include <cuda_runtime.h>
#include <math.h>

// Problem constants
#define B      16
#define C      3
#define H      256
#define W      256
#define HW     65536
#define D      196608
#define NEXP   4
#define TOPK   2
#define HID    64
#define FC     6
#define GSLICE 4

// ---------------- packed f32x2 helpers (sm_100+) --------------------------
typedef unsigned long long u64;

__device__ __forceinline__ u64 pack2(float lo, float hi) {
    u64 r;
    asm("mov.b64 %0, {%1, %2};" : "=l"(r) : "f"(lo), "f"(hi));
    return r;
}
__device__ __forceinline__ void unpack2(u64 v, float& lo, float& hi) {
    asm("mov.b64 {%0, %1}, %2;" : "=f"(lo), "=f"(hi) : "l"(v));
}
__device__ __forceinline__ void fma2(u64& d, u64 a, u64 b) {
    asm("fma.rn.f32x2 %0, %1, %2, %0;" : "+l"(d) : "l"(a), "l"(b));
}

// ---------------- device scratch ------------------------------------------
__device__ float g_refsum[B * C];
__device__ float g_part[B * GSLICE * 8];
__device__ float g_gate[B * 2];
__device__ int   g_eidx[B * 2];

// ---------------- K1: sum ref over spatial per (b,c) ----------------------
__global__ void k_refsum(const float* __restrict__ ref) {
    const float4* p = (const float4*)(ref + (size_t)blockIdx.x * HW);
    float s = 0.f;
    for (int i = threadIdx.x; i < HW / 4; i += 256) {
        float4 v = p[i];
        s += (v.x + v.y) + (v.z + v.w);
    }
    __shared__ float sm[256];
    sm[threadIdx.x] = s;
    __syncthreads();
    for (int st = 128; st > 0; st >>= 1) {
        if (threadIdx.x < st) sm[threadIdx.x] += sm[threadIdx.x + st];
        __syncthreads();
    }
    if (threadIdx.x == 0) g_refsum[blockIdx.x] = sm[0];
}

// ---------------- prompt math (FFT chain collapsed to DC bin) -------------
__device__ void prompt_scales(int b,
                              const float* __restrict__ mod_w1,
                              const float* __restrict__ mod_b1,
                              const float* __restrict__ mod_w2,
                              const float* __restrict__ mod_b2,
                              const float* __restrict__ enh_w,
                              const float* __restrict__ enh_b,
                              const float* __restrict__ fre_prompt,
                              float* sc) {
    float s[3];
#pragma unroll
    for (int c = 0; c < 3; c++) s[c] = g_refsum[b * 3 + c] * (1.f / 256.f);
    float p[12];
#pragma unroll
    for (int i = 0; i < 12; i++) {
        int ci = (i < 6) ? i : i - 6;
        p[i] = (ci < 3) ? s[ci] : 0.f;
    }
    float m1[6];
#pragma unroll
    for (int o = 0; o < 6; o++) {
        float a = mod_b1[o];
#pragma unroll
        for (int i = 0; i < 12; i++) a += mod_w1[o * 12 + i] * p[i];
        m1[o] = fmaxf(a, 0.f);
    }
    float m2[6];
#pragma unroll
    for (int o = 0; o < 6; o++) {
        float a = mod_b2[o];
#pragma unroll
        for (int i = 0; i < 6; i++) a += mod_w2[o * 6 + i] * m1[i];
        m2[o] = a;
    }
    float ein[6];
#pragma unroll
    for (int c = 0; c < 6; c++) ein[c] = m2[c] * fre_prompt[c * (H * (W / 2 + 1))];
    float enh[6];
#pragma unroll
    for (int o = 0; o < 6; o++) {
        float a = enh_b[o];
#pragma unroll
        for (int i = 0; i < 6; i++) a += enh_w[o * 6 + i] * ein[i];
        enh[o] = fmaxf(a, 0.f);
    }
    float v0 = enh[0] * (1.f / 256.f);
    float v1 = enh[1] * (1.f / 256.f);
    float v2 = enh[2] * (1.f / 256.f);
    float mx = fmaxf(v0, fmaxf(v1, v2));
    float e0 = expf(v0 - mx), e1 = expf(v1 - mx), e2 = expf(v2 - mx);
    float inv = 1.f / (e0 + e1 + e2);
    sc[0] = 1.f + e0 * inv;
    sc[1] = 1.f + e1 * inv;
    sc[2] = 1.f + e2 * inv;
}

// ---------------- K2: gating matvecs, grid (B, GSLICE) --------------------
__global__ void k_gate_dots(const float* __restrict__ x,
                            const float* __restrict__ w_gate,
                            const float* __restrict__ w_noise,
                            const float* __restrict__ mod_w1,
                            const float* __restrict__ mod_b1,
                            const float* __restrict__ mod_w2,
                            const float* __restrict__ mod_b2,
                            const float* __restrict__ enh_w,
                            const float* __restrict__ enh_b,
                            const float* __restrict__ fre_prompt) {
    const int b = blockIdx.x, sl = blockIdx.y;
    const int tid = threadIdx.x;
    __shared__ float s_sc[3];
    if (tid == 0) {
        float sc[3];
        prompt_scales(b, mod_w1, mod_b1, mod_w2, mod_b2, enh_w, enh_b,
                      fre_prompt, sc);
        s_sc[0] = sc[0]; s_sc[1] = sc[1]; s_sc[2] = sc[2];
    }
    __syncthreads();
    const float sc0 = s_sc[0], sc1 = s_sc[1], sc2 = s_sc[2];
    const float* xb = x + (size_t)b * D;
    float a[8] = {0, 0, 0, 0, 0, 0, 0, 0};
    const float4* wg4 = (const float4*)w_gate;
    const float4* wn4 = (const float4*)w_noise;
    const int i0 = sl * (D / GSLICE), i1 = i0 + D / GSLICE;
    for (int i = i0 + tid; i < i1; i += 512) {
        float sc = (i < HW) ? sc0 : ((i < 2 * HW) ? sc1 : sc2);
        float xv = xb[i] * sc;
        float4 wg = wg4[i];
        float4 wn = wn4[i];
        a[0] += xv * wg.x; a[1] += xv * wg.y; a[2] += xv * wg.z; a[3] += xv * wg.w;
        a[4] += xv * wn.x; a[5] += xv * wn.y; a[6] += xv * wn.z; a[7] += xv * wn.w;
    }
    __shared__ float sm[512 * 8];
#pragma unroll
    for (int k = 0; k < 8; k++) sm[tid * 8 + k] = a[k];
    __syncthreads();
    for (int st = 256; st > 0; st >>= 1) {
        if (tid < st) {
#pragma unroll
            for (int k = 0; k < 8; k++) sm[tid * 8 + k] += sm[(tid + st) * 8 + k];
        }
        __syncthreads();
    }
    if (tid == 0) {
#pragma unroll
        for (int k = 0; k < 8; k++)
            g_part[(b * GSLICE + sl) * 8 + k] = sm[k];
    }
}

// ---------------- K3: noisy top-k gating + load-balance loss --------------
__device__ __forceinline__ float cv2_4(float a, float b, float c, float d) {
    float m = (a + b + c + d) * 0.25f;
    float va = a - m, vb = b - m, vc = c - m, vd = d - m;
    float var = (va * va + vb * vb + vc * vc + vd * vd) * (1.f / 3.f);
    return var / (m * m + 1e-10f);
}

__global__ void k_finalize(const float* __restrict__ noise,
                           float* __restrict__ out, int out_size) {
    const int lane = threadIdx.x;
    float prob[4] = {0, 0, 0, 0};
    float gates[4] = {0, 0, 0, 0};
    if (lane < B) {
        const int b = lane;
        float lg[8];
#pragma unroll
        for (int k = 0; k < 8; k++) {
            float s = 0.f;
#pragma unroll
            for (int sl = 0; sl < GSLICE; sl++)
                s += g_part[(b * GSLICE + sl) * 8 + k];
            lg[k] = s;
        }
        float clean[4], stdv[4], noisy[4];
#pragma unroll
        for (int e = 0; e < 4; e++) {
            clean[e] = lg[e];
            float z = lg[4 + e];
            float sp = (z > 0.f) ? (z + log1pf(expf(-z))) : log1pf(expf(z));
            stdv[e] = sp + 0.01f;
            noisy[e] = clean[e] + noise[b * 4 + e] * stdv[e];
        }
        float v[4] = {noisy[0], noisy[1], noisy[2], noisy[3]};
        int idx[4] = {0, 1, 2, 3};
#pragma unroll
        for (int s = 0; s < 3; s++) {
            int m = s;
#pragma unroll
            for (int j = s + 1; j < 4; j++)
                if (v[j] > v[m]) m = j;
            float tv = v[s]; v[s] = v[m]; v[m] = tv;
            int ti = idx[s]; idx[s] = idx[m]; idx[m] = ti;
        }
        float t1 = v[1], t2 = v[2];
        float mx = fmaxf(v[0], v[1]);
        float e0 = expf(v[0] - mx), e1 = expf(v[1] - mx);
        float inv = 1.f / (e0 + e1);
        float gA = e0 * inv, gB = e1 * inv;
        gates[idx[0]] = gA;
        gates[idx[1]] = gB;
        g_eidx[b * 2 + 0] = idx[0];
        g_eidx[b * 2 + 1] = idx[1];
        g_gate[b * 2 + 0] = gA;
        g_gate[b * 2 + 1] = gB;
#pragma unroll
        for (int e = 0; e < 4; e++) {
            float thr = (noisy[e] > t2) ? t2 : t1;
            float z = (clean[e] - thr) / stdv[e];
            prob[e] = 0.5f * erfcf(-z * 0.70710678118654752f);
        }
    }
#pragma unroll
    for (int off = 16; off > 0; off >>= 1) {
#pragma unroll
        for (int e = 0; e < 4; e++) {
            prob[e]  += __shfl_down_sync(0xffffffffu, prob[e], off);
            gates[e] += __shfl_down_sync(0xffffffffu, gates[e], off);
        }
    }
    if (lane == 0) {
        float loss = (cv2_4(gates[0], gates[1], gates[2], gates[3]) +
                      cv2_4(prob[0], prob[1], prob[2], prob[3])) * 0.01f;
        if (out_size > B * HW) out[B * HW] = loss;
    }
}

// ---------------- K4: fused sparse expert convs (packed f32x2) ------------
// 288 threads, 3 blocks/SM. Chunk = 32 channels = 16 channel-PAIRS.
// conv1 task = (pair, row), ONE 18-wide pass (a01[18] u64): pair-weights and
// x-window overlap loaded once per iteration (-15% smem wavefronts on the
// binding L1 pipe). The ic loop is NOT unrolled (unroll 1) to keep the
// ptxas-visible body small — 54 fma2 per trip instead of a 162-op chain —
// avoiding the compile-time blowup suspected of killing R14/R15 builds.
// conv2 reads packed h pairs with LDS.64, folds lanes into persistent
// scalar acc2[16] each iteration. 'part' overlays hs2 at the end.
#define TDIM 16
#define NTHR 288
#define CHP  32
#define XW   21          // xs row stride (floats, odd)
#define HP2  343         // hs2 per-pair block stride in u64 (18*19+1 skew)
#define PICL 274

__global__ void __launch_bounds__(NTHR, 3)
k_expert(const float* __restrict__ x,
         const float* __restrict__ ew1, const float* __restrict__ eb1,
         const float* __restrict__ ew2, const float* __restrict__ eb2,
         float* __restrict__ out) {
    const int b = blockIdx.z, tY = blockIdx.y, tX = blockIdx.x;
    const int tid = threadIdx.x;

    __shared__ float xs[3 * 20 * XW];     // 20160 B
    __shared__ u64   hs2[16 * HP2];       // 43904 B (reused as 'part')
    __shared__ u64   w1p[16 * 27];        // 3456 B  (packed ch-pairs)
    __shared__ u64   w2p[16 * 9];         // 1152 B  (packed, gate-scaled)
    __shared__ float b1s[CHP];

    // load x tile (+halo 2), shared by both experts
    const int gy0 = tY * TDIM - 2, gx0 = tX * TDIM - 2;
    for (int i = tid; i < 3 * 20 * 20; i += NTHR) {
        int c = i / 400, r = (i / 20) % 20, col = i % 20;
        int gy = gy0 + r, gx = gx0 + col;
        float v = 0.f;
        if ((unsigned)gy < 256u && (unsigned)gx < 256u)
            v = x[((size_t)(b * 3 + c) << 16) + (gy << 8) + gx];
        xs[(c * 20 + r) * XW + col] = v;
    }

    const bool interior = (tY > 0) && (tY < H / TDIM - 1) &&
                          (tX > 0) && (tX < W / TDIM - 1);

    // conv1 task: (pair, row)
    const int c1_p  = tid / 18;          // 0..15
    const int c1_yy = tid % 18;          // 0..17
    const bool rowok = interior ||
        (unsigned)(tY * TDIM + c1_yy - 1) < (unsigned)H;

    const int cy = tid >> 4, cp = tid & 15;   // conv2 task (tid < 256)

    const int   eA = g_eidx[b * 2 + 0], eB = g_eidx[b * 2 + 1];
    const float gA = g_gate[b * 2 + 0], gB = g_gate[b * 2 + 1];

    float acc2[16];
#pragma unroll
    for (int j = 0; j < 16; j++) acc2[j] = 0.f;

    for (int it = 0; it < 4; it++) {
        const int e   = (it < 2) ? eA : eB;
        const float g = (it < 2) ? gA : gB;
        const int ch  = it & 1;

        __syncthreads(); // prior conv2 reads of hs2/w2p done (covers xs fill)
        {
            const float* W1 = ew1 + e * (HID * 27) + ch * (CHP * 27);
            for (int i = tid; i < 16 * 27; i += NTHR) {
                int p = i / 27, k = i % 27;
                w1p[i] = pack2(W1[(2 * p) * 27 + k], W1[(2 * p + 1) * 27 + k]);
            }
            const float* W2 = ew2 + e * (HID * 9) + ch * (CHP * 9);
            for (int i = tid; i < 16 * 9; i += NTHR) {
                int p = i / 9, k = i % 9;
                w2p[i] = pack2(g * W2[(2 * p) * 9 + k], g * W2[(2 * p + 1) * 9 + k]);
            }
            if (tid < CHP) b1s[tid] = eb1[e * HID + ch * CHP + tid];
        }
        __syncthreads();

        // conv1 + ReLU: channel-pair per thread, ONE 18-wide pass.
        // ic loop deliberately NOT unrolled (compile-size control).
        {
            const u64 bp = pack2(b1s[2 * c1_p], b1s[2 * c1_p + 1]);
            u64 a01[18];
#pragma unroll
            for (int j = 0; j < 18; j++) a01[j] = bp;
#pragma unroll 1
            for (int ic = 0; ic < 3; ic++) {
#pragma unroll
                for (int ky = 0; ky < 3; ky++) {
                    const float* row = &xs[(ic * 20 + c1_yy + ky) * XW];
                    const u64* wp = &w1p[c1_p * 27 + ic * 9 + ky * 3];
                    const u64 wa = wp[0], wb = wp[1], wc = wp[2];
                    float r0 = row[0], r1 = row[1];
                    u64 rp0 = pack2(r0, r0), rp1 = pack2(r1, r1);
#pragma unroll
                    for (int j = 0; j < 18; j++) {
                        float r2 = row[j + 2];
                        u64 rp2 = pack2(r2, r2);
                        fma2(a01[j], rp0, wa);
                        fma2(a01[j], rp1, wb);
                        fma2(a01[j], rp2, wc);
                        rp0 = rp1; rp1 = rp2;
                    }
                }
            }
            u64* hrow = &hs2[c1_p * HP2 + c1_yy * 19];
            if (interior) {
#pragma unroll
                for (int j = 0; j < 18; j++) {
                    float lo, hi;
                    unpack2(a01[j], lo, hi);
                    hrow[j] = pack2(fmaxf(lo, 0.f), fmaxf(hi, 0.f));
                }
            } else {
                // conv2 SAME padding: h == 0 outside the image
#pragma unroll
                for (int j = 0; j < 18; j++) {
                    float lo, hi;
                    unpack2(a01[j], lo, hi);
                    const bool ok = rowok &&
                        (unsigned)(tX * TDIM + j - 1) < (unsigned)W;
                    hrow[j] = ok ? pack2(fmaxf(lo, 0.f), fmaxf(hi, 0.f))
                                 : 0ull;
                }
            }
        }
        __syncthreads();

        // conv2: pair cp, sliding window over packed h rows; lane-split
        // partials in accP, folded into scalar acc2 once per iteration.
        if (tid < 256) {
            u64 accP[16];
#pragma unroll
            for (int j = 0; j < 16; j++) accP[j] = 0ull;
            const u64* w2row = &w2p[cp * 9];
#pragma unroll
            for (int ky = 0; ky < 3; ky++) {
                const u64* row = &hs2[cp * HP2 + (cy + ky) * 19];
                const u64 wa = w2row[ky * 3], wb = w2row[ky * 3 + 1],
                          wc = w2row[ky * 3 + 2];
                u64 rp0 = row[0], rp1 = row[1];
#pragma unroll
                for (int j = 0; j < 16; j++) {
                    u64 rp2 = row[j + 2];
                    fma2(accP[j], rp0, wa);
                    fma2(accP[j], rp1, wb);
                    fma2(accP[j], rp2, wc);
                    rp0 = rp1; rp1 = rp2;
                }
            }
#pragma unroll
            for (int j = 0; j < 16; j++) {
                float lo, hi;
                unpack2(accP[j], lo, hi);
                acc2[j] += lo + hi;
            }
        }
    }

    __syncthreads(); // all hs2 reads done -> overlay part
    float* part = (float*)hs2;
    if (tid < 256) {
        float* pp = &part[cp * PICL + cy * 17];
#pragma unroll
        for (int j = 0; j < 16; j++) pp[j] = acc2[j];
    }
    __syncthreads();

    if (tid < 256) {
        const int oy = tid >> 4, ox = tid & 15;
        float yacc = 0.f;
#pragma unroll
        for (int icl = 0; icl < 16; icl++)
            yacc += part[icl * PICL + oy * 17 + ox];
        yacc += gA * eb2[eA] + gB * eb2[eB];
        out[((size_t)b << 16) + ((tY * TDIM + oy) << 8) + (tX * TDIM + ox)] = yacc;
    }
}

// ---------------- no-op pad launch (keeps k_expert at profile slot 3) ----
__global__ void k_noop() {}

// ---------------- launch ---------------------------------------------------
extern "C" void kernel_launch(void* const* d_in, const int* in_sizes, int n_in,
                              void* d_out, int out_size) {
    const float* x          = (const float*)d_in[0];
    const float* ref        = (const float*)d_in[1];
    const float* noise      = (const float*)d_in[2];
    const float* mod_w1     = (const float*)d_in[3];
    const float* mod_b1     = (const float*)d_in[4];
    const float* mod_w2     = (const float*)d_in[5];
    const float* mod_b2     = (const float*)d_in[6];
    const float* enh_w      = (const float*)d_in[7];
    const float* enh_b      = (const float*)d_in[8];
    const float* fre_prompt = (const float*)d_in[9];
    const float* w_gate     = (const float*)d_in[10];
    const float* w_noise    = (const float*)d_in[11];
    const float* ew1        = (const float*)d_in[12];
    const float* eb1        = (const float*)d_in[13];
    const float* ew2        = (const float*)d_in[14];
    const float* eb2        = (const float*)d_in[15];
    float* out = (float*)d_out;

    k_refsum<<<B * C, 256>>>(ref);                                       // 0
    k_gate_dots<<<dim3(B, GSLICE), 512>>>(x, w_gate, w_noise, mod_w1,
                                          mod_b1, mod_w2, mod_b2, enh_w,
                                          enh_b, fre_prompt);            // 1
    k_finalize<<<1, 32>>>(noise, out, out_size);                         // 2
    k_expert<<<dim3(W / TDIM, H / TDIM, B), NTHR>>>(x, ew1, eb1,
                                                    ew2, eb2, out);      // 3
    k_noop<<<1, 32>>>();                                                 // 4
}